// round 1
// baseline (speedup 1.0000x reference)
#include <cuda_runtime.h>
#include <math.h>

#define HIDDEN 1024
#define NHEADS 16
#define HEADD  64
#define BATCH  4
#define SEQ    2048
#define MTOK   (BATCH*SEQ)          // 8192
#define BNH    (BATCH*NHEADS)       // 64
#define PER_BN ((size_t)SEQ*HEADD)  // 131072

// Scratch: Q,K,V,O in [b][n][s][h] layout (head-major), fp32.
__device__ float g_Q[BATCH*NHEADS*SEQ*HEADD];
__device__ float g_K[BATCH*NHEADS*SEQ*HEADD];
__device__ float g_V[BATCH*NHEADS*SEQ*HEADD];
__device__ float g_O[BATCH*NHEADS*SEQ*HEADD];

// ---------------------------------------------------------------------------
// Kernel 1: QKV projection GEMM.
//   C[8192, 3072] = A @ Wqkv, where A = x + pos for columns < 2048 (Q,K) and
//   A = x for columns >= 2048 (V). Output scattered to g_Q/g_K/g_V in
//   [b][n][s][h] layout.
//   128x128x8 tiles, 256 threads, 8x8 per-thread micro-tile.
// ---------------------------------------------------------------------------
__global__ __launch_bounds__(256) void qkv_gemm(
    const float* __restrict__ x, const float* __restrict__ pos,
    const float* __restrict__ Wqkv)
{
    __shared__ float As[8][128];  // [k][m]
    __shared__ float Bs[8][128];  // [k][n]

    const int tid = threadIdx.x;
    const int m0 = blockIdx.y * 128;
    const int n0 = blockIdx.x * 128;
    const bool add_pos = (n0 < 2 * HIDDEN);   // Q,K columns

    const int tx = tid & 15, ty = tid >> 4;

    // A load mapping: 128 rows x 2 float4
    const int arow = tid >> 1, acg = tid & 1;
    const int gm = m0 + arow;
    const int srow = gm & (SEQ - 1);
    // B load mapping: 8 rows x 32 float4
    const int brow = tid >> 5, bcg = tid & 31;

    float acc[8][8];
#pragma unroll
    for (int i = 0; i < 8; i++)
#pragma unroll
        for (int j = 0; j < 8; j++) acc[i][j] = 0.f;

    // prefetch tile 0
    float4 av = *(const float4*)(x + (size_t)gm * HIDDEN + acg * 4);
    if (add_pos) {
        float4 pv = *(const float4*)(pos + (size_t)srow * HIDDEN + acg * 4);
        av.x += pv.x; av.y += pv.y; av.z += pv.z; av.w += pv.w;
    }
    float4 bv = *(const float4*)(Wqkv + (size_t)brow * (3 * HIDDEN) + n0 + bcg * 4);

    for (int k0 = 0; k0 < HIDDEN; k0 += 8) {
        __syncthreads();
        As[acg * 4 + 0][arow] = av.x;
        As[acg * 4 + 1][arow] = av.y;
        As[acg * 4 + 2][arow] = av.z;
        As[acg * 4 + 3][arow] = av.w;
        *(float4*)(&Bs[brow][bcg * 4]) = bv;
        __syncthreads();

        if (k0 + 8 < HIDDEN) {
            int kn = k0 + 8;
            av = *(const float4*)(x + (size_t)gm * HIDDEN + kn + acg * 4);
            if (add_pos) {
                float4 pv = *(const float4*)(pos + (size_t)srow * HIDDEN + kn + acg * 4);
                av.x += pv.x; av.y += pv.y; av.z += pv.z; av.w += pv.w;
            }
            bv = *(const float4*)(Wqkv + (size_t)(kn + brow) * (3 * HIDDEN) + n0 + bcg * 4);
        }

#pragma unroll
        for (int kk = 0; kk < 8; kk++) {
            float4 a0 = *(const float4*)(&As[kk][ty * 4]);
            float4 a1 = *(const float4*)(&As[kk][64 + ty * 4]);
            float4 b0 = *(const float4*)(&Bs[kk][tx * 4]);
            float4 b1 = *(const float4*)(&Bs[kk][64 + tx * 4]);
            float a[8] = {a0.x, a0.y, a0.z, a0.w, a1.x, a1.y, a1.z, a1.w};
            float b[8] = {b0.x, b0.y, b0.z, b0.w, b1.x, b1.y, b1.z, b1.w};
#pragma unroll
            for (int i = 0; i < 8; i++)
#pragma unroll
                for (int j = 0; j < 8; j++) acc[i][j] += a[i] * b[j];
        }
    }

    // epilogue: scatter to Q/K/V [b][n][s][h]
#pragma unroll
    for (int i = 0; i < 8; i++) {
        int m = m0 + ((i < 4) ? (ty * 4 + i) : (64 + ty * 4 + i - 4));
        int bb = m >> 11, ss = m & 2047;
#pragma unroll
        for (int j = 0; j < 8; j++) {
            int nn = n0 + ((j < 4) ? (tx * 4 + j) : (64 + tx * 4 + j - 4));
            int reg = nn >> 10;             // 0=Q 1=K 2=V (uniform per block)
            int head = (nn >> 6) & 15;
            int h = nn & 63;
            float* dst = (reg == 0) ? g_Q : (reg == 1) ? g_K : g_V;
            dst[(((size_t)bb * NHEADS + head) * SEQ + ss) * HEADD + h] = acc[i][j];
        }
    }
}

// ---------------------------------------------------------------------------
// Kernel 2: causal flash attention per (b*n, q-tile).
//   64 queries x 32-key tiles, 128 threads (16 ty x 8 tx), per-thread:
//   4x4 of S, 4x8 of O. Online softmax with 8-lane shuffle reductions.
// ---------------------------------------------------------------------------
__global__ __launch_bounds__(128) void attn_kernel()
{
    __shared__ float Qt[64][64];   // [h][q], pre-scaled by 1/8
    __shared__ float Kt[64][36];   // [h][key] (pad 36 for store conflicts + f4 align)
    __shared__ float Vs[32][64];   // [key][h]
    __shared__ float Ps[64][36];   // [q][key]

    const int tid = threadIdx.x;
    const int tx = tid & 7, ty = tid >> 3;
    const int bn = blockIdx.x;     // 0..63
    const int qt = blockIdx.y;     // 0..31

    const float* Qb = g_Q + (size_t)bn * PER_BN + (size_t)qt * 64 * HEADD;
    const float* Kb = g_K + (size_t)bn * PER_BN;
    const float* Vb = g_V + (size_t)bn * PER_BN;
    float*       Ob = g_O + (size_t)bn * PER_BN + (size_t)qt * 64 * HEADD;

    // load Q tile transposed + scaled (once)
#pragma unroll
    for (int r = 0; r < 8; r++) {
        int lin = tid + r * 128;           // float4 index, 1024 total
        int q = lin >> 4, hg = lin & 15;
        float4 v = *(const float4*)(Qb + q * HEADD + hg * 4);
        Qt[hg * 4 + 0][q] = v.x * 0.125f;
        Qt[hg * 4 + 1][q] = v.y * 0.125f;
        Qt[hg * 4 + 2][q] = v.z * 0.125f;
        Qt[hg * 4 + 3][q] = v.w * 0.125f;
    }

    float accO[4][8];
#pragma unroll
    for (int i = 0; i < 4; i++)
#pragma unroll
        for (int c = 0; c < 8; c++) accO[i][c] = 0.f;
    float mrow[4] = {-1e30f, -1e30f, -1e30f, -1e30f};
    float lrow[4] = {0.f, 0.f, 0.f, 0.f};

    const int qg0 = qt * 64;
    const int ntiles = 2 * qt + 2;

    for (int kt = 0; kt < ntiles; kt++) {
        __syncthreads();   // prev iter's Ps/Vs reads done; also covers Qt on iter 0
        const int kbase = kt * 32;
#pragma unroll
        for (int r = 0; r < 4; r++) {
            int lin = tid + r * 128;       // float4 index, 512 total
            int key = lin >> 4, hg = lin & 15;
            float4 kv = *(const float4*)(Kb + (size_t)(kbase + key) * HEADD + hg * 4);
            Kt[hg * 4 + 0][key] = kv.x;
            Kt[hg * 4 + 1][key] = kv.y;
            Kt[hg * 4 + 2][key] = kv.z;
            Kt[hg * 4 + 3][key] = kv.w;
            float4 vv = *(const float4*)(Vb + (size_t)(kbase + key) * HEADD + hg * 4);
            *(float4*)(&Vs[key][hg * 4]) = vv;
        }
        __syncthreads();

        // S = (Q/8) K^T
        float sacc[4][4];
#pragma unroll
        for (int i = 0; i < 4; i++)
#pragma unroll
            for (int j = 0; j < 4; j++) sacc[i][j] = 0.f;
#pragma unroll 8
        for (int h = 0; h < 64; h++) {
            float4 a = *(const float4*)(&Qt[h][ty * 4]);
            float4 b = *(const float4*)(&Kt[h][tx * 4]);
            float av[4] = {a.x, a.y, a.z, a.w};
            float bv[4] = {b.x, b.y, b.z, b.w};
#pragma unroll
            for (int i = 0; i < 4; i++)
#pragma unroll
                for (int j = 0; j < 4; j++) sacc[i][j] += av[i] * bv[j];
        }

        // causal mask (only last two tiles can cross the diagonal)
        if (kbase + 31 > qg0) {
#pragma unroll
            for (int i = 0; i < 4; i++) {
                int qg = qg0 + ty * 4 + i;
#pragma unroll
                for (int j = 0; j < 4; j++) {
                    int kg = kbase + tx * 4 + j;
                    if (kg > qg) sacc[i][j] = -1e30f;
                }
            }
        }

        // online softmax
#pragma unroll
        for (int i = 0; i < 4; i++) {
            float mloc = fmaxf(fmaxf(sacc[i][0], sacc[i][1]),
                               fmaxf(sacc[i][2], sacc[i][3]));
#pragma unroll
            for (int off = 1; off < 8; off <<= 1)
                mloc = fmaxf(mloc, __shfl_xor_sync(0xffffffffu, mloc, off));
            float mn = fmaxf(mrow[i], mloc);
            float scale = __expf(mrow[i] - mn);
            mrow[i] = mn;
            float p0 = __expf(sacc[i][0] - mn);
            float p1 = __expf(sacc[i][1] - mn);
            float p2 = __expf(sacc[i][2] - mn);
            float p3 = __expf(sacc[i][3] - mn);
            float lloc = (p0 + p1) + (p2 + p3);
#pragma unroll
            for (int off = 1; off < 8; off <<= 1)
                lloc += __shfl_xor_sync(0xffffffffu, lloc, off);
            lrow[i] = lrow[i] * scale + lloc;
#pragma unroll
            for (int c = 0; c < 8; c++) accO[i][c] *= scale;
            float4 pw = make_float4(p0, p1, p2, p3);
            *(float4*)(&Ps[ty * 4 + i][tx * 4]) = pw;
        }
        __syncthreads();

        // O += P V
#pragma unroll 4
        for (int kk = 0; kk < 32; kk++) {
            float p0 = Ps[ty * 4 + 0][kk];
            float p1 = Ps[ty * 4 + 1][kk];
            float p2 = Ps[ty * 4 + 2][kk];
            float p3 = Ps[ty * 4 + 3][kk];
            float4 v0 = *(const float4*)(&Vs[kk][tx * 8]);
            float4 v1 = *(const float4*)(&Vs[kk][tx * 8 + 4]);
            float vv[8] = {v0.x, v0.y, v0.z, v0.w, v1.x, v1.y, v1.z, v1.w};
#pragma unroll
            for (int c = 0; c < 8; c++) {
                accO[0][c] += p0 * vv[c];
                accO[1][c] += p1 * vv[c];
                accO[2][c] += p2 * vv[c];
                accO[3][c] += p3 * vv[c];
            }
        }
    }

    // normalize + write
#pragma unroll
    for (int i = 0; i < 4; i++) {
        float inv = 1.0f / lrow[i];
        int q = ty * 4 + i;
        float4 o0 = make_float4(accO[i][0] * inv, accO[i][1] * inv,
                                accO[i][2] * inv, accO[i][3] * inv);
        float4 o1 = make_float4(accO[i][4] * inv, accO[i][5] * inv,
                                accO[i][6] * inv, accO[i][7] * inv);
        *(float4*)(Ob + q * HEADD + tx * 8)     = o0;
        *(float4*)(Ob + q * HEADD + tx * 8 + 4) = o1;
    }
}

// ---------------------------------------------------------------------------
// Kernel 3: output projection GEMM.
//   out[8192,1024] = A @ Wo, A gathered from g_O [b][n][s][h] (fused
//   head-merge transpose). Same 128x128x8 scheme.
// ---------------------------------------------------------------------------
__global__ __launch_bounds__(256) void out_gemm(
    const float* __restrict__ Wo, float* __restrict__ out)
{
    __shared__ float As[8][128];
    __shared__ float Bs[8][128];

    const int tid = threadIdx.x;
    const int m0 = blockIdx.y * 128;
    const int n0 = blockIdx.x * 128;
    const int tx = tid & 15, ty = tid >> 4;

    const int arow = tid >> 1, acg = tid & 1;
    const int gm = m0 + arow;
    const int bb = gm >> 11, ss = gm & 2047;
    const int brow = tid >> 5, bcg = tid & 31;

    float acc[8][8];
#pragma unroll
    for (int i = 0; i < 8; i++)
#pragma unroll
        for (int j = 0; j < 8; j++) acc[i][j] = 0.f;

    auto loadA = [&](int k0) -> float4 {
        int gk = k0 + acg * 4;
        int head = gk >> 6, h = gk & 63;
        return *(const float4*)(g_O + (((size_t)bb * NHEADS + head) * SEQ + ss) * HEADD + h);
    };

    float4 av = loadA(0);
    float4 bv = *(const float4*)(Wo + (size_t)brow * HIDDEN + n0 + bcg * 4);

    for (int k0 = 0; k0 < HIDDEN; k0 += 8) {
        __syncthreads();
        As[acg * 4 + 0][arow] = av.x;
        As[acg * 4 + 1][arow] = av.y;
        As[acg * 4 + 2][arow] = av.z;
        As[acg * 4 + 3][arow] = av.w;
        *(float4*)(&Bs[brow][bcg * 4]) = bv;
        __syncthreads();

        if (k0 + 8 < HIDDEN) {
            av = loadA(k0 + 8);
            bv = *(const float4*)(Wo + (size_t)(k0 + 8 + brow) * HIDDEN + n0 + bcg * 4);
        }

#pragma unroll
        for (int kk = 0; kk < 8; kk++) {
            float4 a0 = *(const float4*)(&As[kk][ty * 4]);
            float4 a1 = *(const float4*)(&As[kk][64 + ty * 4]);
            float4 b0 = *(const float4*)(&Bs[kk][tx * 4]);
            float4 b1 = *(const float4*)(&Bs[kk][64 + tx * 4]);
            float a[8] = {a0.x, a0.y, a0.z, a0.w, a1.x, a1.y, a1.z, a1.w};
            float b[8] = {b0.x, b0.y, b0.z, b0.w, b1.x, b1.y, b1.z, b1.w};
#pragma unroll
            for (int i = 0; i < 8; i++)
#pragma unroll
                for (int j = 0; j < 8; j++) acc[i][j] += a[i] * b[j];
        }
    }

#pragma unroll
    for (int i = 0; i < 8; i++) {
        int m = m0 + ((i < 4) ? (ty * 4 + i) : (64 + ty * 4 + i - 4));
        float4 c0 = make_float4(acc[i][0], acc[i][1], acc[i][2], acc[i][3]);
        float4 c1 = make_float4(acc[i][4], acc[i][5], acc[i][6], acc[i][7]);
        *(float4*)(out + (size_t)m * HIDDEN + n0 + tx * 4)      = c0;
        *(float4*)(out + (size_t)m * HIDDEN + n0 + 64 + tx * 4) = c1;
    }
}

// ---------------------------------------------------------------------------
extern "C" void kernel_launch(void* const* d_in, const int* in_sizes, int n_in,
                              void* d_out, int out_size)
{
    const float* x    = (const float*)d_in[0];
    const float* pos  = (const float*)d_in[1];
    const float* Wqkv = (const float*)d_in[2];
    const float* Wo   = (const float*)d_in[3];
    float* out = (float*)d_out;

    qkv_gemm<<<dim3(3 * HIDDEN / 128, MTOK / 128), 256>>>(x, pos, Wqkv);
    attn_kernel<<<dim3(BNH, SEQ / 64), 128>>>();
    out_gemm<<<dim3(HIDDEN / 128, MTOK / 128), 256>>>(Wo, out);
}

// round 2
// speedup vs baseline: 1.0009x; 1.0009x over previous
#include <cuda_runtime.h>
#include <math.h>

#define HIDDEN 1024
#define NHEADS 16
#define HEADD  64
#define BATCH  4
#define SEQ    2048
#define MTOK   (BATCH*SEQ)          // 8192
#define BNH    (BATCH*NHEADS)       // 64
#define PER_BN ((size_t)SEQ*HEADD)  // 131072

// Scratch: Q,K,V,O in [b][n][s][h] layout (head-major), fp32.
__device__ float g_Q[BATCH*NHEADS*SEQ*HEADD];
__device__ float g_K[BATCH*NHEADS*SEQ*HEADD];
__device__ float g_V[BATCH*NHEADS*SEQ*HEADD];
__device__ float g_O[BATCH*NHEADS*SEQ*HEADD];

// ---------------------------------------------------------------------------
// Kernel 1: QKV projection GEMM.
//   C[8192, 3072] = A @ Wqkv, where A = x + pos for columns < 2048 (Q,K) and
//   A = x for columns >= 2048 (V). Output scattered to g_Q/g_K/g_V in
//   [b][n][s][h] layout.
//   128x128x8 tiles, 256 threads, 8x8 per-thread micro-tile.
// ---------------------------------------------------------------------------
__global__ __launch_bounds__(256) void qkv_gemm(
    const float* __restrict__ x, const float* __restrict__ pos,
    const float* __restrict__ Wqkv)
{
    __shared__ float As[8][128];  // [k][m]
    __shared__ float Bs[8][128];  // [k][n]

    const int tid = threadIdx.x;
    const int m0 = blockIdx.y * 128;
    const int n0 = blockIdx.x * 128;
    const bool add_pos = (n0 < 2 * HIDDEN);   // Q,K columns

    const int tx = tid & 15, ty = tid >> 4;

    // A load mapping: 128 rows x 2 float4
    const int arow = tid >> 1, acg = tid & 1;
    const int gm = m0 + arow;
    const int srow = gm & (SEQ - 1);
    // B load mapping: 8 rows x 32 float4
    const int brow = tid >> 5, bcg = tid & 31;

    float acc[8][8];
#pragma unroll
    for (int i = 0; i < 8; i++)
#pragma unroll
        for (int j = 0; j < 8; j++) acc[i][j] = 0.f;

    // prefetch tile 0
    float4 av = *(const float4*)(x + (size_t)gm * HIDDEN + acg * 4);
    if (add_pos) {
        float4 pv = *(const float4*)(pos + (size_t)srow * HIDDEN + acg * 4);
        av.x += pv.x; av.y += pv.y; av.z += pv.z; av.w += pv.w;
    }
    float4 bv = *(const float4*)(Wqkv + (size_t)brow * (3 * HIDDEN) + n0 + bcg * 4);

    for (int k0 = 0; k0 < HIDDEN; k0 += 8) {
        __syncthreads();
        As[acg * 4 + 0][arow] = av.x;
        As[acg * 4 + 1][arow] = av.y;
        As[acg * 4 + 2][arow] = av.z;
        As[acg * 4 + 3][arow] = av.w;
        *(float4*)(&Bs[brow][bcg * 4]) = bv;
        __syncthreads();

        if (k0 + 8 < HIDDEN) {
            int kn = k0 + 8;
            av = *(const float4*)(x + (size_t)gm * HIDDEN + kn + acg * 4);
            if (add_pos) {
                float4 pv = *(const float4*)(pos + (size_t)srow * HIDDEN + kn + acg * 4);
                av.x += pv.x; av.y += pv.y; av.z += pv.z; av.w += pv.w;
            }
            bv = *(const float4*)(Wqkv + (size_t)(kn + brow) * (3 * HIDDEN) + n0 + bcg * 4);
        }

#pragma unroll
        for (int kk = 0; kk < 8; kk++) {
            float4 a0 = *(const float4*)(&As[kk][ty * 4]);
            float4 a1 = *(const float4*)(&As[kk][64 + ty * 4]);
            float4 b0 = *(const float4*)(&Bs[kk][tx * 4]);
            float4 b1 = *(const float4*)(&Bs[kk][64 + tx * 4]);
            float a[8] = {a0.x, a0.y, a0.z, a0.w, a1.x, a1.y, a1.z, a1.w};
            float b[8] = {b0.x, b0.y, b0.z, b0.w, b1.x, b1.y, b1.z, b1.w};
#pragma unroll
            for (int i = 0; i < 8; i++)
#pragma unroll
                for (int j = 0; j < 8; j++) acc[i][j] += a[i] * b[j];
        }
    }

    // epilogue: scatter to Q/K/V [b][n][s][h]
#pragma unroll
    for (int i = 0; i < 8; i++) {
        int m = m0 + ((i < 4) ? (ty * 4 + i) : (64 + ty * 4 + i - 4));
        int bb = m >> 11, ss = m & 2047;
#pragma unroll
        for (int j = 0; j < 8; j++) {
            int nn = n0 + ((j < 4) ? (tx * 4 + j) : (64 + tx * 4 + j - 4));
            int reg = nn >> 10;             // 0=Q 1=K 2=V (uniform per block)
            int head = (nn >> 6) & 15;
            int h = nn & 63;
            float* dst = (reg == 0) ? g_Q : (reg == 1) ? g_K : g_V;
            dst[(((size_t)bb * NHEADS + head) * SEQ + ss) * HEADD + h] = acc[i][j];
        }
    }
}

// ---------------------------------------------------------------------------
// Kernel 2: causal flash attention per (b*n, q-tile).
//   64 queries x 32-key tiles, 128 threads (16 ty x 8 tx), per-thread:
//   4x4 of S, 4x8 of O. Online softmax with 8-lane shuffle reductions.
// ---------------------------------------------------------------------------
__global__ __launch_bounds__(128) void attn_kernel()
{
    __shared__ float Qt[64][64];   // [h][q], pre-scaled by 1/8
    __shared__ float Kt[64][36];   // [h][key] (pad 36 for store conflicts + f4 align)
    __shared__ float Vs[32][64];   // [key][h]
    __shared__ float Ps[64][36];   // [q][key]

    const int tid = threadIdx.x;
    const int tx = tid & 7, ty = tid >> 3;
    const int bn = blockIdx.x;     // 0..63
    const int qt = blockIdx.y;     // 0..31

    const float* Qb = g_Q + (size_t)bn * PER_BN + (size_t)qt * 64 * HEADD;
    const float* Kb = g_K + (size_t)bn * PER_BN;
    const float* Vb = g_V + (size_t)bn * PER_BN;
    float*       Ob = g_O + (size_t)bn * PER_BN + (size_t)qt * 64 * HEADD;

    // load Q tile transposed + scaled (once)
#pragma unroll
    for (int r = 0; r < 8; r++) {
        int lin = tid + r * 128;           // float4 index, 1024 total
        int q = lin >> 4, hg = lin & 15;
        float4 v = *(const float4*)(Qb + q * HEADD + hg * 4);
        Qt[hg * 4 + 0][q] = v.x * 0.125f;
        Qt[hg * 4 + 1][q] = v.y * 0.125f;
        Qt[hg * 4 + 2][q] = v.z * 0.125f;
        Qt[hg * 4 + 3][q] = v.w * 0.125f;
    }

    float accO[4][8];
#pragma unroll
    for (int i = 0; i < 4; i++)
#pragma unroll
        for (int c = 0; c < 8; c++) accO[i][c] = 0.f;
    float mrow[4] = {-1e30f, -1e30f, -1e30f, -1e30f};
    float lrow[4] = {0.f, 0.f, 0.f, 0.f};

    const int qg0 = qt * 64;
    const int ntiles = 2 * qt + 2;

    for (int kt = 0; kt < ntiles; kt++) {
        __syncthreads();   // prev iter's Ps/Vs reads done; also covers Qt on iter 0
        const int kbase = kt * 32;
#pragma unroll
        for (int r = 0; r < 4; r++) {
            int lin = tid + r * 128;       // float4 index, 512 total
            int key = lin >> 4, hg = lin & 15;
            float4 kv = *(const float4*)(Kb + (size_t)(kbase + key) * HEADD + hg * 4);
            Kt[hg * 4 + 0][key] = kv.x;
            Kt[hg * 4 + 1][key] = kv.y;
            Kt[hg * 4 + 2][key] = kv.z;
            Kt[hg * 4 + 3][key] = kv.w;
            float4 vv = *(const float4*)(Vb + (size_t)(kbase + key) * HEADD + hg * 4);
            *(float4*)(&Vs[key][hg * 4]) = vv;
        }
        __syncthreads();

        // S = (Q/8) K^T
        float sacc[4][4];
#pragma unroll
        for (int i = 0; i < 4; i++)
#pragma unroll
            for (int j = 0; j < 4; j++) sacc[i][j] = 0.f;
#pragma unroll 8
        for (int h = 0; h < 64; h++) {
            float4 a = *(const float4*)(&Qt[h][ty * 4]);
            float4 b = *(const float4*)(&Kt[h][tx * 4]);
            float av[4] = {a.x, a.y, a.z, a.w};
            float bv[4] = {b.x, b.y, b.z, b.w};
#pragma unroll
            for (int i = 0; i < 4; i++)
#pragma unroll
                for (int j = 0; j < 4; j++) sacc[i][j] += av[i] * bv[j];
        }

        // causal mask (only last two tiles can cross the diagonal)
        if (kbase + 31 > qg0) {
#pragma unroll
            for (int i = 0; i < 4; i++) {
                int qg = qg0 + ty * 4 + i;
#pragma unroll
                for (int j = 0; j < 4; j++) {
                    int kg = kbase + tx * 4 + j;
                    if (kg > qg) sacc[i][j] = -1e30f;
                }
            }
        }

        // online softmax
#pragma unroll
        for (int i = 0; i < 4; i++) {
            float mloc = fmaxf(fmaxf(sacc[i][0], sacc[i][1]),
                               fmaxf(sacc[i][2], sacc[i][3]));
#pragma unroll
            for (int off = 1; off < 8; off <<= 1)
                mloc = fmaxf(mloc, __shfl_xor_sync(0xffffffffu, mloc, off));
            float mn = fmaxf(mrow[i], mloc);
            float scale = __expf(mrow[i] - mn);
            mrow[i] = mn;
            float p0 = __expf(sacc[i][0] - mn);
            float p1 = __expf(sacc[i][1] - mn);
            float p2 = __expf(sacc[i][2] - mn);
            float p3 = __expf(sacc[i][3] - mn);
            float lloc = (p0 + p1) + (p2 + p3);
#pragma unroll
            for (int off = 1; off < 8; off <<= 1)
                lloc += __shfl_xor_sync(0xffffffffu, lloc, off);
            lrow[i] = lrow[i] * scale + lloc;
#pragma unroll
            for (int c = 0; c < 8; c++) accO[i][c] *= scale;
            float4 pw = make_float4(p0, p1, p2, p3);
            *(float4*)(&Ps[ty * 4 + i][tx * 4]) = pw;
        }
        __syncthreads();

        // O += P V
#pragma unroll 4
        for (int kk = 0; kk < 32; kk++) {
            float p0 = Ps[ty * 4 + 0][kk];
            float p1 = Ps[ty * 4 + 1][kk];
            float p2 = Ps[ty * 4 + 2][kk];
            float p3 = Ps[ty * 4 + 3][kk];
            float4 v0 = *(const float4*)(&Vs[kk][tx * 8]);
            float4 v1 = *(const float4*)(&Vs[kk][tx * 8 + 4]);
            float vv[8] = {v0.x, v0.y, v0.z, v0.w, v1.x, v1.y, v1.z, v1.w};
#pragma unroll
            for (int c = 0; c < 8; c++) {
                accO[0][c] += p0 * vv[c];
                accO[1][c] += p1 * vv[c];
                accO[2][c] += p2 * vv[c];
                accO[3][c] += p3 * vv[c];
            }
        }
    }

    // normalize + write
#pragma unroll
    for (int i = 0; i < 4; i++) {
        float inv = 1.0f / lrow[i];
        int q = ty * 4 + i;
        float4 o0 = make_float4(accO[i][0] * inv, accO[i][1] * inv,
                                accO[i][2] * inv, accO[i][3] * inv);
        float4 o1 = make_float4(accO[i][4] * inv, accO[i][5] * inv,
                                accO[i][6] * inv, accO[i][7] * inv);
        *(float4*)(Ob + q * HEADD + tx * 8)     = o0;
        *(float4*)(Ob + q * HEADD + tx * 8 + 4) = o1;
    }
}

// ---------------------------------------------------------------------------
// Kernel 3: output projection GEMM.
//   out[8192,1024] = A @ Wo, A gathered from g_O [b][n][s][h] (fused
//   head-merge transpose). Same 128x128x8 scheme.
// ---------------------------------------------------------------------------
__global__ __launch_bounds__(256) void out_gemm(
    const float* __restrict__ Wo, float* __restrict__ out)
{
    __shared__ float As[8][128];
    __shared__ float Bs[8][128];

    const int tid = threadIdx.x;
    const int m0 = blockIdx.y * 128;
    const int n0 = blockIdx.x * 128;
    const int tx = tid & 15, ty = tid >> 4;

    const int arow = tid >> 1, acg = tid & 1;
    const int gm = m0 + arow;
    const int bb = gm >> 11, ss = gm & 2047;
    const int brow = tid >> 5, bcg = tid & 31;

    float acc[8][8];
#pragma unroll
    for (int i = 0; i < 8; i++)
#pragma unroll
        for (int j = 0; j < 8; j++) acc[i][j] = 0.f;

    auto loadA = [&](int k0) -> float4 {
        int gk = k0 + acg * 4;
        int head = gk >> 6, h = gk & 63;
        return *(const float4*)(g_O + (((size_t)bb * NHEADS + head) * SEQ + ss) * HEADD + h);
    };

    float4 av = loadA(0);
    float4 bv = *(const float4*)(Wo + (size_t)brow * HIDDEN + n0 + bcg * 4);

    for (int k0 = 0; k0 < HIDDEN; k0 += 8) {
        __syncthreads();
        As[acg * 4 + 0][arow] = av.x;
        As[acg * 4 + 1][arow] = av.y;
        As[acg * 4 + 2][arow] = av.z;
        As[acg * 4 + 3][arow] = av.w;
        *(float4*)(&Bs[brow][bcg * 4]) = bv;
        __syncthreads();

        if (k0 + 8 < HIDDEN) {
            av = loadA(k0 + 8);
            bv = *(const float4*)(Wo + (size_t)(k0 + 8 + brow) * HIDDEN + n0 + bcg * 4);
        }

#pragma unroll
        for (int kk = 0; kk < 8; kk++) {
            float4 a0 = *(const float4*)(&As[kk][ty * 4]);
            float4 a1 = *(const float4*)(&As[kk][64 + ty * 4]);
            float4 b0 = *(const float4*)(&Bs[kk][tx * 4]);
            float4 b1 = *(const float4*)(&Bs[kk][64 + tx * 4]);
            float a[8] = {a0.x, a0.y, a0.z, a0.w, a1.x, a1.y, a1.z, a1.w};
            float b[8] = {b0.x, b0.y, b0.z, b0.w, b1.x, b1.y, b1.z, b1.w};
#pragma unroll
            for (int i = 0; i < 8; i++)
#pragma unroll
                for (int j = 0; j < 8; j++) acc[i][j] += a[i] * b[j];
        }
    }

#pragma unroll
    for (int i = 0; i < 8; i++) {
        int m = m0 + ((i < 4) ? (ty * 4 + i) : (64 + ty * 4 + i - 4));
        float4 c0 = make_float4(acc[i][0], acc[i][1], acc[i][2], acc[i][3]);
        float4 c1 = make_float4(acc[i][4], acc[i][5], acc[i][6], acc[i][7]);
        *(float4*)(out + (size_t)m * HIDDEN + n0 + tx * 4)      = c0;
        *(float4*)(out + (size_t)m * HIDDEN + n0 + 64 + tx * 4) = c1;
    }
}

// ---------------------------------------------------------------------------
extern "C" void kernel_launch(void* const* d_in, const int* in_sizes, int n_in,
                              void* d_out, int out_size)
{
    const float* x    = (const float*)d_in[0];
    const float* pos  = (const float*)d_in[1];
    const float* Wqkv = (const float*)d_in[2];
    const float* Wo   = (const float*)d_in[3];
    float* out = (float*)d_out;

    qkv_gemm<<<dim3(3 * HIDDEN / 128, MTOK / 128), 256>>>(x, pos, Wqkv);
    attn_kernel<<<dim3(BNH, SEQ / 64), 128>>>();
    out_gemm<<<dim3(HIDDEN / 128, MTOK / 128), 256>>>(Wo, out);
}

// round 4
// speedup vs baseline: 1.8374x; 1.8358x over previous
#include <cuda_runtime.h>
#include <cuda_bf16.h>
#include <cstdint>
#include <math.h>

#define HIDDEN 1024
#define NHEADS 16
#define HEADD  64
#define BATCH  4
#define SEQ    2048
#define MTOK   (BATCH*SEQ)
#define BNH    (BATCH*NHEADS)

// packed bf16 hi/lo pairs as u32
__device__ __align__(16) uint32_t g_Xh[MTOK*512],  g_Xl[MTOK*512];
__device__ __align__(16) uint32_t g_Peh[SEQ*512],  g_Pel[SEQ*512];
__device__ __align__(16) uint32_t g_WTh[3*HIDDEN*512], g_WTl[3*HIDDEN*512];
__device__ __align__(16) uint32_t g_WoTh[HIDDEN*512],  g_WoTl[HIDDEN*512];
__device__ __align__(16) float    g_pos[SEQ*2*HIDDEN];
__device__ __align__(16) uint32_t g_Qh[BNH*SEQ*32], g_Ql[BNH*SEQ*32];
__device__ __align__(16) uint32_t g_Kh[BNH*SEQ*32], g_Kl[BNH*SEQ*32];
__device__ __align__(16) uint32_t g_VTh[BNH*HEADD*1024], g_VTl[BNH*HEADD*1024];
__device__ __align__(16) uint32_t g_Oh[BNH*SEQ*32], g_Ol[BNH*SEQ*32];

__device__ __forceinline__ void split_pack(float a, float b, uint32_t& hi, uint32_t& lo) {
    __nv_bfloat16 ah = __float2bfloat16(a);
    __nv_bfloat16 bh = __float2bfloat16(b);
    __nv_bfloat16 al = __float2bfloat16(a - __bfloat162float(ah));
    __nv_bfloat16 bl = __float2bfloat16(b - __bfloat162float(bh));
    hi = (uint32_t)__bfloat16_as_ushort(ah) | ((uint32_t)__bfloat16_as_ushort(bh) << 16);
    lo = (uint32_t)__bfloat16_as_ushort(al) | ((uint32_t)__bfloat16_as_ushort(bl) << 16);
}

__device__ __forceinline__ void mma16816(float c[4], const uint32_t a[4],
                                         uint32_t b0, uint32_t b1) {
    asm volatile(
        "mma.sync.aligned.m16n8k16.row.col.f32.bf16.bf16.f32 "
        "{%0,%1,%2,%3},{%4,%5,%6,%7},{%8,%9},{%0,%1,%2,%3};\n"
        : "+f"(c[0]), "+f"(c[1]), "+f"(c[2]), "+f"(c[3])
        : "r"(a[0]), "r"(a[1]), "r"(a[2]), "r"(a[3]), "r"(b0), "r"(b1));
}

__global__ void cvt_x_kernel(const float* __restrict__ x, const float* __restrict__ pe) {
    int i = blockIdx.x * blockDim.x + threadIdx.x;
    const int NX = MTOK * 512, NP = SEQ * 512;
    if (i < NX) {
        float2 v = ((const float2*)x)[i];
        split_pack(v.x, v.y, g_Xh[i], g_Xl[i]);
    } else if (i < NX + NP) {
        int j = i - NX;
        float2 v = ((const float2*)pe)[j];
        split_pack(v.x, v.y, g_Peh[j], g_Pel[j]);
    }
}

// transpose-pack weights: pair = (W[2kp][n], W[2kp+1][n]) at [n][kp]
__global__ void cvt_w_kernel(const float* __restrict__ Wqkv, const float* __restrict__ Wo) {
    int i = blockIdx.x * blockDim.x + threadIdx.x;
    const int N1 = 3 * HIDDEN * 512, N2 = HIDDEN * 512;
    if (i < N1) {
        int n = i % (3 * HIDDEN), kp = i / (3 * HIDDEN);
        split_pack(Wqkv[(size_t)(2 * kp) * 3072 + n], Wqkv[(size_t)(2 * kp + 1) * 3072 + n],
                   g_WTh[(size_t)n * 512 + kp], g_WTl[(size_t)n * 512 + kp]);
    } else if (i < N1 + N2) {
        int j = i - N1;
        int n = j % HIDDEN, kp = j / HIDDEN;
        split_pack(Wo[(size_t)(2 * kp) * HIDDEN + n], Wo[(size_t)(2 * kp + 1) * HIDDEN + n],
                   g_WoTh[(size_t)n * 512 + kp], g_WoTl[(size_t)n * 512 + kp]);
    }
}

// 128x128 tile mma core, K-step = 32 floats (16 pairs)
__device__ __forceinline__ void mma_tile128(
    const uint32_t (*Ahs)[20], const uint32_t (*Als)[20],
    const uint32_t (*Bhs)[20], const uint32_t (*Bls)[20],
    int wm, int wn, int g, int tig, float acc[4][4][4])
{
#pragma unroll
    for (int ks = 0; ks < 2; ks++) {
        uint32_t ah[4][4], al[4][4];
        const int kp = ks * 8 + tig;
#pragma unroll
        for (int mi = 0; mi < 4; mi++) {
            int r = wm * 64 + mi * 16 + g;
            ah[mi][0] = Ahs[r][kp];     ah[mi][1] = Ahs[r + 8][kp];
            ah[mi][2] = Ahs[r][kp + 4]; ah[mi][3] = Ahs[r + 8][kp + 4];
            al[mi][0] = Als[r][kp];     al[mi][1] = Als[r + 8][kp];
            al[mi][2] = Als[r][kp + 4]; al[mi][3] = Als[r + 8][kp + 4];
        }
#pragma unroll
        for (int nj = 0; nj < 4; nj++) {
            int r = wn * 32 + nj * 8 + g;
            uint32_t bh0 = Bhs[r][kp], bh1 = Bhs[r][kp + 4];
            uint32_t bl0 = Bls[r][kp], bl1 = Bls[r][kp + 4];
#pragma unroll
            for (int mi = 0; mi < 4; mi++) {
                mma16816(acc[mi][nj], ah[mi], bh0, bh1);
                mma16816(acc[mi][nj], ah[mi], bl0, bl1);
                mma16816(acc[mi][nj], al[mi], bh0, bh1);
            }
        }
    }
}

#define GEMM_PROLOG()                                                          \
    __shared__ __align__(16) uint32_t Ah[128][20], Al[128][20];                \
    __shared__ __align__(16) uint32_t Bh[128][20], Bl[128][20];                \
    const int tid = threadIdx.x, lane = tid & 31, wid = tid >> 5;              \
    const int g = lane >> 2, tig = lane & 3;                                   \
    const int wm = wid >> 2, wn = wid & 3;                                     \
    const int m0 = blockIdx.y * 128, n0 = blockIdx.x * 128;                    \
    const int lrow = tid >> 1, lc = (tid & 1) * 8;                             \
    float acc[4][4][4];                                                        \
    for (int a_ = 0; a_ < 4; a_++)                                             \
        for (int b_ = 0; b_ < 4; b_++)                                         \
            for (int c_ = 0; c_ < 4; c_++) acc[a_][b_][c_] = 0.f;

#define GEMM_MAINLOOP(pAh_, pAl_, pBh_, pBl_)                                  \
    uint4 rah0 = *(const uint4*)(pAh_);     uint4 rah1 = *(const uint4*)(pAh_ + 4); \
    uint4 ral0 = *(const uint4*)(pAl_);     uint4 ral1 = *(const uint4*)(pAl_ + 4); \
    uint4 rbh0 = *(const uint4*)(pBh_);     uint4 rbh1 = *(const uint4*)(pBh_ + 4); \
    uint4 rbl0 = *(const uint4*)(pBl_);     uint4 rbl1 = *(const uint4*)(pBl_ + 4); \
    for (int kt = 0; kt < 32; kt++) {                                          \
        __syncthreads();                                                       \
        *(uint4*)&Ah[lrow][lc] = rah0;  *(uint4*)&Ah[lrow][lc + 4] = rah1;     \
        *(uint4*)&Al[lrow][lc] = ral0;  *(uint4*)&Al[lrow][lc + 4] = ral1;     \
        *(uint4*)&Bh[lrow][lc] = rbh0;  *(uint4*)&Bh[lrow][lc + 4] = rbh1;     \
        *(uint4*)&Bl[lrow][lc] = rbl0;  *(uint4*)&Bl[lrow][lc + 4] = rbl1;     \
        __syncthreads();                                                       \
        if (kt < 31) {                                                         \
            int off = (kt + 1) * 16;                                           \
            rah0 = *(const uint4*)(pAh_ + off); rah1 = *(const uint4*)(pAh_ + off + 4); \
            ral0 = *(const uint4*)(pAl_ + off); ral1 = *(const uint4*)(pAl_ + off + 4); \
            rbh0 = *(const uint4*)(pBh_ + off); rbh1 = *(const uint4*)(pBh_ + off + 4); \
            rbl0 = *(const uint4*)(pBl_ + off); rbl1 = *(const uint4*)(pBl_ + off + 4); \
        }                                                                      \
        mma_tile128(Ah, Al, Bh, Bl, wm, wn, g, tig, acc);                      \
    }

// pos @ Wqkv[:, :2048]
__global__ __launch_bounds__(256) void pos_gemm() {
    GEMM_PROLOG();
    const uint32_t* pAh = g_Peh + (size_t)(m0 + lrow) * 512 + lc;
    const uint32_t* pAl = g_Pel + (size_t)(m0 + lrow) * 512 + lc;
    const uint32_t* pBh = g_WTh + (size_t)(n0 + lrow) * 512 + lc;
    const uint32_t* pBl = g_WTl + (size_t)(n0 + lrow) * 512 + lc;
    GEMM_MAINLOOP(pAh, pAl, pBh, pBl);
#pragma unroll
    for (int mi = 0; mi < 4; mi++)
#pragma unroll
        for (int nj = 0; nj < 4; nj++) {
            int m = m0 + wm * 64 + mi * 16 + g;
            int nn = n0 + wn * 32 + nj * 8 + 2 * tig;
            *(float2*)(g_pos + (size_t)m * 2048 + nn) = make_float2(acc[mi][nj][0], acc[mi][nj][1]);
            *(float2*)(g_pos + (size_t)(m + 8) * 2048 + nn) = make_float2(acc[mi][nj][2], acc[mi][nj][3]);
        }
}

__global__ __launch_bounds__(256) void qkv_gemm() {
    GEMM_PROLOG();
    const uint32_t* pAh = g_Xh + (size_t)(m0 + lrow) * 512 + lc;
    const uint32_t* pAl = g_Xl + (size_t)(m0 + lrow) * 512 + lc;
    const uint32_t* pBh = g_WTh + (size_t)(n0 + lrow) * 512 + lc;
    const uint32_t* pBl = g_WTl + (size_t)(n0 + lrow) * 512 + lc;
    GEMM_MAINLOOP(pAh, pAl, pBh, pBl);

    const int reg = n0 >> 10;   // 0=Q 1=K 2=V, uniform per block
#pragma unroll
    for (int mi = 0; mi < 4; mi++) {
#pragma unroll
        for (int nj = 0; nj < 4; nj++) {
            int m = m0 + wm * 64 + mi * 16 + g;
            int nn = n0 + wn * 32 + nj * 8 + 2 * tig;
            int bb = m >> 11, ss = m & 2047;
            float c0 = acc[mi][nj][0], c1 = acc[mi][nj][1];
            float c2 = acc[mi][nj][2], c3 = acc[mi][nj][3];
            if (reg < 2) {
                float2 pa = *(const float2*)(g_pos + (size_t)ss * 2048 + nn);
                float2 pb = *(const float2*)(g_pos + (size_t)(ss + 8) * 2048 + nn);
                c0 += pa.x; c1 += pa.y; c2 += pb.x; c3 += pb.y;
                if (reg == 0) { c0 *= 0.125f; c1 *= 0.125f; c2 *= 0.125f; c3 *= 0.125f; }
                int head = (nn >> 6) & 15, hp = (nn & 63) >> 1;
                size_t bn = (size_t)bb * 16 + head;
                size_t i0 = (bn * SEQ + ss) * 32 + hp;
                size_t i1 = (bn * SEQ + ss + 8) * 32 + hp;
                uint32_t h01, l01, h23, l23;
                split_pack(c0, c1, h01, l01);
                split_pack(c2, c3, h23, l23);
                if (reg == 0) { g_Qh[i0] = h01; g_Ql[i0] = l01; g_Qh[i1] = h23; g_Ql[i1] = l23; }
                else          { g_Kh[i0] = h01; g_Kl[i0] = l01; g_Kh[i1] = h23; g_Kl[i1] = l23; }
            } else {
                // V: pair along sequence via lane exchange (g <-> g^1)
                float o0 = __shfl_xor_sync(0xffffffffu, c0, 4);
                float o1 = __shfl_xor_sync(0xffffffffu, c1, 4);
                float o2 = __shfl_xor_sync(0xffffffffu, c2, 4);
                float o3 = __shfl_xor_sync(0xffffffffu, c3, 4);
                if ((g & 1) == 0) {
                    int head = (nn >> 6) & 15;
                    size_t bn = (size_t)bb * 16 + head;
                    int h0 = nn & 63;
                    int sp0 = ss >> 1;
                    uint32_t hi, lo;
                    size_t b0 = (bn * HEADD + h0) * 1024;
                    size_t b1 = (bn * HEADD + h0 + 1) * 1024;
                    split_pack(c0, o0, hi, lo); g_VTh[b0 + sp0] = hi;     g_VTl[b0 + sp0] = lo;
                    split_pack(c1, o1, hi, lo); g_VTh[b1 + sp0] = hi;     g_VTl[b1 + sp0] = lo;
                    split_pack(c2, o2, hi, lo); g_VTh[b0 + sp0 + 4] = hi; g_VTl[b0 + sp0 + 4] = lo;
                    split_pack(c3, o3, hi, lo); g_VTh[b1 + sp0 + 4] = hi; g_VTl[b1 + sp0 + 4] = lo;
                }
            }
        }
    }
}

// flash attention: 64-query block, 64-key tiles, 4 warps
__global__ __launch_bounds__(128) void attn_kernel() {
    __shared__ __align__(16) uint32_t Kh[64][44], Kl[64][44];  // reused as P
    __shared__ __align__(16) uint32_t Vh[64][44], Vl[64][44];  // V^T [h][key-pair]
    uint32_t (*Ph)[44] = Kh;
    uint32_t (*Pl)[44] = Kl;

    const int tid = threadIdx.x, lane = tid & 31, w = tid >> 5;
    const int g = lane >> 2, tig = lane & 3;
    const int bn = blockIdx.x, qt = blockIdx.y;

    const int qr = qt * 64 + 16 * w + g;
    const uint32_t* qbh = g_Qh + ((size_t)bn * SEQ + qr) * 32 + tig;
    const uint32_t* qbl = g_Ql + ((size_t)bn * SEQ + qr) * 32 + tig;
    uint32_t qah[4][4], qal[4][4];
#pragma unroll
    for (int ks = 0; ks < 4; ks++) {
        qah[ks][0] = qbh[ks * 8];     qah[ks][1] = qbh[256 + ks * 8];
        qah[ks][2] = qbh[ks * 8 + 4]; qah[ks][3] = qbh[256 + ks * 8 + 4];
        qal[ks][0] = qbl[ks * 8];     qal[ks][1] = qbl[256 + ks * 8];
        qal[ks][2] = qbl[ks * 8 + 4]; qal[ks][3] = qbl[256 + ks * 8 + 4];
    }

    float o[8][4];
#pragma unroll
    for (int nt = 0; nt < 8; nt++)
#pragma unroll
        for (int c = 0; c < 4; c++) o[nt][c] = 0.f;
    float mrun0 = -1e30f, mrun1 = -1e30f, lrun0 = 0.f, lrun1 = 0.f;

    const int lrow = tid >> 1, cb = (tid & 1) * 16;
    const uint32_t* kgh = g_Kh + ((size_t)bn * SEQ + lrow) * 32 + cb;
    const uint32_t* kgl = g_Kl + ((size_t)bn * SEQ + lrow) * 32 + cb;
    const uint32_t* vgh = g_VTh + ((size_t)bn * HEADD + lrow) * 1024 + cb;
    const uint32_t* vgl = g_VTl + ((size_t)bn * HEADD + lrow) * 1024 + cb;

    for (int kt = 0; kt <= qt; kt++) {
        const int kbase = kt * 64;
        __syncthreads();
        {
            size_t ko = (size_t)kbase * 32, vo = (size_t)kt * 32;
#pragma unroll
            for (int i = 0; i < 4; i++) {
                *(uint4*)&Kh[lrow][cb + 4 * i] = *(const uint4*)(kgh + ko + 4 * i);
                *(uint4*)&Kl[lrow][cb + 4 * i] = *(const uint4*)(kgl + ko + 4 * i);
                *(uint4*)&Vh[lrow][cb + 4 * i] = *(const uint4*)(vgh + vo + 4 * i);
                *(uint4*)&Vl[lrow][cb + 4 * i] = *(const uint4*)(vgl + vo + 4 * i);
            }
        }
        __syncthreads();

        // S = Qs @ K^T
        float sacc[8][4];
#pragma unroll
        for (int nt = 0; nt < 8; nt++)
#pragma unroll
            for (int c = 0; c < 4; c++) sacc[nt][c] = 0.f;
#pragma unroll
        for (int ks = 0; ks < 4; ks++) {
            const int kp = ks * 8 + tig;
#pragma unroll
            for (int nt = 0; nt < 8; nt++) {
                int r = nt * 8 + g;
                uint32_t bh0 = Kh[r][kp], bh1 = Kh[r][kp + 4];
                uint32_t bl0 = Kl[r][kp], bl1 = Kl[r][kp + 4];
                mma16816(sacc[nt], qah[ks], bh0, bh1);
                mma16816(sacc[nt], qah[ks], bl0, bl1);
                mma16816(sacc[nt], qal[ks], bh0, bh1);
            }
        }

        if (kt == qt) {   // diagonal tile mask
#pragma unroll
            for (int nt = 0; nt < 8; nt++) {
                int kg = kbase + nt * 8 + 2 * tig;
                if (kg > qr)         sacc[nt][0] = -1e30f;
                if (kg + 1 > qr)     sacc[nt][1] = -1e30f;
                if (kg > qr + 8)     sacc[nt][2] = -1e30f;
                if (kg + 1 > qr + 8) sacc[nt][3] = -1e30f;
            }
        }

        // online softmax
        float ml0 = -1e30f, ml1 = -1e30f;
#pragma unroll
        for (int nt = 0; nt < 8; nt++) {
            ml0 = fmaxf(ml0, fmaxf(sacc[nt][0], sacc[nt][1]));
            ml1 = fmaxf(ml1, fmaxf(sacc[nt][2], sacc[nt][3]));
        }
        ml0 = fmaxf(ml0, __shfl_xor_sync(0xffffffffu, ml0, 1));
        ml0 = fmaxf(ml0, __shfl_xor_sync(0xffffffffu, ml0, 2));
        ml1 = fmaxf(ml1, __shfl_xor_sync(0xffffffffu, ml1, 1));
        ml1 = fmaxf(ml1, __shfl_xor_sync(0xffffffffu, ml1, 2));
        float mn0 = fmaxf(mrun0, ml0), mn1 = fmaxf(mrun1, ml1);
        float scl0 = __expf(mrun0 - mn0), scl1 = __expf(mrun1 - mn1);
        mrun0 = mn0; mrun1 = mn1;
        float ls0 = 0.f, ls1 = 0.f;
#pragma unroll
        for (int nt = 0; nt < 8; nt++) {
            float p0 = __expf(sacc[nt][0] - mn0);
            float p1 = __expf(sacc[nt][1] - mn0);
            float p2 = __expf(sacc[nt][2] - mn1);
            float p3 = __expf(sacc[nt][3] - mn1);
            ls0 += p0 + p1; ls1 += p2 + p3;
            sacc[nt][0] = p0; sacc[nt][1] = p1; sacc[nt][2] = p2; sacc[nt][3] = p3;
            o[nt][0] *= scl0; o[nt][1] *= scl0; o[nt][2] *= scl1; o[nt][3] *= scl1;
        }
        lrun0 = lrun0 * scl0 + ls0;
        lrun1 = lrun1 * scl1 + ls1;

        __syncthreads();   // all warps done reading K before P overwrite
#pragma unroll
        for (int nt = 0; nt < 8; nt++) {
            uint32_t hi, lo;
            split_pack(sacc[nt][0], sacc[nt][1], hi, lo);
            Ph[16 * w + g][nt * 4 + tig] = hi;      Pl[16 * w + g][nt * 4 + tig] = lo;
            split_pack(sacc[nt][2], sacc[nt][3], hi, lo);
            Ph[16 * w + g + 8][nt * 4 + tig] = hi;  Pl[16 * w + g + 8][nt * 4 + tig] = lo;
        }
        __syncwarp();

        // O += P @ V
#pragma unroll
        for (int ks = 0; ks < 4; ks++) {
            const int kp = ks * 8 + tig;
            uint32_t pah[4], pal[4];
            pah[0] = Ph[16 * w + g][kp];     pah[1] = Ph[16 * w + g + 8][kp];
            pah[2] = Ph[16 * w + g][kp + 4]; pah[3] = Ph[16 * w + g + 8][kp + 4];
            pal[0] = Pl[16 * w + g][kp];     pal[1] = Pl[16 * w + g + 8][kp];
            pal[2] = Pl[16 * w + g][kp + 4]; pal[3] = Pl[16 * w + g + 8][kp + 4];
#pragma unroll
            for (int nt = 0; nt < 8; nt++) {
                int r = nt * 8 + g;
                uint32_t bh0 = Vh[r][kp], bh1 = Vh[r][kp + 4];
                uint32_t bl0 = Vl[r][kp], bl1 = Vl[r][kp + 4];
                mma16816(o[nt], pah, bh0, bh1);
                mma16816(o[nt], pah, bl0, bl1);
                mma16816(o[nt], pal, bh0, bh1);
            }
        }
    }

    lrun0 += __shfl_xor_sync(0xffffffffu, lrun0, 1);
    lrun0 += __shfl_xor_sync(0xffffffffu, lrun0, 2);
    lrun1 += __shfl_xor_sync(0xffffffffu, lrun1, 1);
    lrun1 += __shfl_xor_sync(0xffffffffu, lrun1, 2);
    float inv0 = 1.f / lrun0, inv1 = 1.f / lrun1;
    size_t ob0 = ((size_t)bn * SEQ + qr) * 32 + tig;
    size_t ob1 = ((size_t)bn * SEQ + qr + 8) * 32 + tig;
#pragma unroll
    for (int nt = 0; nt < 8; nt++) {
        uint32_t hi, lo;
        split_pack(o[nt][0] * inv0, o[nt][1] * inv0, hi, lo);
        g_Oh[ob0 + nt * 4] = hi;  g_Ol[ob0 + nt * 4] = lo;
        split_pack(o[nt][2] * inv1, o[nt][3] * inv1, hi, lo);
        g_Oh[ob1 + nt * 4] = hi;  g_Ol[ob1 + nt * 4] = lo;
    }
}

__global__ __launch_bounds__(256) void out_gemm(float* __restrict__ out) {
    GEMM_PROLOG();
    const int arow = m0 + lrow;
    const int bb = arow >> 11, ss = arow & 2047;
    const uint32_t* pBh = g_WoTh + (size_t)(n0 + lrow) * 512 + lc;
    const uint32_t* pBl = g_WoTl + (size_t)(n0 + lrow) * 512 + lc;

    auto abase = [&](int kp) -> size_t {
        int head = kp >> 5;
        return (((size_t)bb * 16 + head) * SEQ + ss) * 32 + (kp & 31);
    };
    uint4 rah0, rah1, ral0, ral1, rbh0, rbh1, rbl0, rbl1;
    {
        size_t a0 = abase(lc), a1 = abase(lc + 4);
        rah0 = *(const uint4*)(g_Oh + a0); rah1 = *(const uint4*)(g_Oh + a1);
        ral0 = *(const uint4*)(g_Ol + a0); ral1 = *(const uint4*)(g_Ol + a1);
    }
    rbh0 = *(const uint4*)(pBh); rbh1 = *(const uint4*)(pBh + 4);
    rbl0 = *(const uint4*)(pBl); rbl1 = *(const uint4*)(pBl + 4);
    for (int kt = 0; kt < 32; kt++) {
        __syncthreads();
        *(uint4*)&Ah[lrow][lc] = rah0;  *(uint4*)&Ah[lrow][lc + 4] = rah1;
        *(uint4*)&Al[lrow][lc] = ral0;  *(uint4*)&Al[lrow][lc + 4] = ral1;
        *(uint4*)&Bh[lrow][lc] = rbh0;  *(uint4*)&Bh[lrow][lc + 4] = rbh1;
        *(uint4*)&Bl[lrow][lc] = rbl0;  *(uint4*)&Bl[lrow][lc + 4] = rbl1;
        __syncthreads();
        if (kt < 31) {
            int off = (kt + 1) * 16;
            size_t a0 = abase(off + lc), a1 = abase(off + lc + 4);
            rah0 = *(const uint4*)(g_Oh + a0); rah1 = *(const uint4*)(g_Oh + a1);
            ral0 = *(const uint4*)(g_Ol + a0); ral1 = *(const uint4*)(g_Ol + a1);
            rbh0 = *(const uint4*)(pBh + off); rbh1 = *(const uint4*)(pBh + off + 4);
            rbl0 = *(const uint4*)(pBl + off); rbl1 = *(const uint4*)(pBl + off + 4);
        }
        mma_tile128(Ah, Al, Bh, Bl, wm, wn, g, tig, acc);
    }

#pragma unroll
    for (int mi = 0; mi < 4; mi++)
#pragma unroll
        for (int nj = 0; nj < 4; nj++) {
            int m = m0 + wm * 64 + mi * 16 + g;
            int nn = n0 + wn * 32 + nj * 8 + 2 * tig;
            *(float2*)(out + (size_t)m * HIDDEN + nn) = make_float2(acc[mi][nj][0], acc[mi][nj][1]);
            *(float2*)(out + (size_t)(m + 8) * HIDDEN + nn) = make_float2(acc[mi][nj][2], acc[mi][nj][3]);
        }
}

extern "C" void kernel_launch(void* const* d_in, const int* in_sizes, int n_in,
                              void* d_out, int out_size)
{
    const float* x    = (const float*)d_in[0];
    const float* pos  = (const float*)d_in[1];
    const float* Wqkv = (const float*)d_in[2];
    const float* Wo   = (const float*)d_in[3];
    float* out = (float*)d_out;

    cvt_x_kernel<<<(MTOK * 512 + SEQ * 512 + 255) / 256, 256>>>(x, pos);
    cvt_w_kernel<<<(4 * HIDDEN * 512 + 255) / 256, 256>>>(Wqkv, Wo);
    pos_gemm<<<dim3(2 * HIDDEN / 128, SEQ / 128), 256>>>();
    qkv_gemm<<<dim3(3 * HIDDEN / 128, MTOK / 128), 256>>>();
    attn_kernel<<<dim3(BNH, SEQ / 64), 128>>>();
    out_gemm<<<dim3(HIDDEN / 128, MTOK / 128), 256>>>(out);
}

// round 6
// speedup vs baseline: 1.9182x; 1.0440x over previous
#include <cuda_runtime.h>
#include <cuda_bf16.h>
#include <cstdint>
#include <math.h>

#define HIDDEN 1024
#define NHEADS 16
#define HEADD  64
#define BATCH  4
#define SEQ    2048
#define MTOK   (BATCH*SEQ)
#define BNH    (BATCH*NHEADS)

// packed bf16 hi/lo pairs as u32
__device__ __align__(16) uint32_t g_Xh[MTOK*512],  g_Xl[MTOK*512];
__device__ __align__(16) uint32_t g_Peh[SEQ*512],  g_Pel[SEQ*512];
__device__ __align__(16) uint32_t g_WTh[3*HIDDEN*512], g_WTl[3*HIDDEN*512];
__device__ __align__(16) uint32_t g_WoTh[HIDDEN*512],  g_WoTl[HIDDEN*512];
__device__ __align__(16) float    g_pos[SEQ*2*HIDDEN];
__device__ __align__(16) uint32_t g_Qh[BNH*SEQ*32], g_Ql[BNH*SEQ*32];
__device__ __align__(16) uint32_t g_Kh[BNH*SEQ*32], g_Kl[BNH*SEQ*32];
__device__ __align__(16) uint32_t g_VTh[BNH*HEADD*1024], g_VTl[BNH*HEADD*1024];
__device__ __align__(16) uint32_t g_Oh[BNH*SEQ*32], g_Ol[BNH*SEQ*32];

__device__ __forceinline__ void split_pack(float a, float b, uint32_t& hi, uint32_t& lo) {
    __nv_bfloat16 ah = __float2bfloat16(a);
    __nv_bfloat16 bh = __float2bfloat16(b);
    __nv_bfloat16 al = __float2bfloat16(a - __bfloat162float(ah));
    __nv_bfloat16 bl = __float2bfloat16(b - __bfloat162float(bh));
    hi = (uint32_t)__bfloat16_as_ushort(ah) | ((uint32_t)__bfloat16_as_ushort(bh) << 16);
    lo = (uint32_t)__bfloat16_as_ushort(al) | ((uint32_t)__bfloat16_as_ushort(bl) << 16);
}

__device__ __forceinline__ void mma16816(float c[4], const uint32_t a[4],
                                         uint32_t b0, uint32_t b1) {
    asm volatile(
        "mma.sync.aligned.m16n8k16.row.col.f32.bf16.bf16.f32 "
        "{%0,%1,%2,%3},{%4,%5,%6,%7},{%8,%9},{%0,%1,%2,%3};\n"
        : "+f"(c[0]), "+f"(c[1]), "+f"(c[2]), "+f"(c[3])
        : "r"(a[0]), "r"(a[1]), "r"(a[2]), "r"(a[3]), "r"(b0), "r"(b1));
}

__device__ __forceinline__ void ldsm4(uint32_t r[4], uint32_t addr) {
    asm volatile("ldmatrix.sync.aligned.m8n8.x4.shared.b16 {%0,%1,%2,%3}, [%4];\n"
                 : "=r"(r[0]), "=r"(r[1]), "=r"(r[2]), "=r"(r[3]) : "r"(addr));
}

__device__ __forceinline__ void cpa(uint32_t saddr, const void* g) {
    asm volatile("cp.async.cg.shared.global [%0], [%1], 16;\n" :: "r"(saddr), "l"(g) : "memory");
}
#define CPCOMMIT() asm volatile("cp.async.commit_group;\n" ::: "memory")
#define CPWAIT1()  asm volatile("cp.async.wait_group 1;\n" ::: "memory")

__global__ void cvt_x_kernel(const float* __restrict__ x, const float* __restrict__ pe) {
    int i = blockIdx.x * blockDim.x + threadIdx.x;
    const int NX = MTOK * 512, NP = SEQ * 512;
    if (i < NX) {
        float2 v = ((const float2*)x)[i];
        split_pack(v.x, v.y, g_Xh[i], g_Xl[i]);
    } else if (i < NX + NP) {
        int j = i - NX;
        float2 v = ((const float2*)pe)[j];
        split_pack(v.x, v.y, g_Peh[j], g_Pel[j]);
    }
}

__global__ void cvt_w_kernel(const float* __restrict__ Wqkv, const float* __restrict__ Wo) {
    int i = blockIdx.x * blockDim.x + threadIdx.x;
    const int N1 = 3 * HIDDEN * 512, N2 = HIDDEN * 512;
    if (i < N1) {
        int n = i % (3 * HIDDEN), kp = i / (3 * HIDDEN);
        split_pack(Wqkv[(size_t)(2 * kp) * 3072 + n], Wqkv[(size_t)(2 * kp + 1) * 3072 + n],
                   g_WTh[(size_t)n * 512 + kp], g_WTl[(size_t)n * 512 + kp]);
    } else if (i < N1 + N2) {
        int j = i - N1;
        int n = j % HIDDEN, kp = j / HIDDEN;
        split_pack(Wo[(size_t)(2 * kp) * HIDDEN + n], Wo[(size_t)(2 * kp + 1) * HIDDEN + n],
                   g_WoTh[(size_t)n * 512 + kp], g_WoTl[(size_t)n * 512 + kp]);
    }
}

// ---------------- GEMM: 128x128 tile, K-step 32 floats, cp.async 3-stage ----
// dyn smem: 3 buffers x (Ah[128][20], Al, Bh, Bl) u32; 40960B each.
extern __shared__ __align__(16) uint32_t dynsm[];

#define GEMM_PROLOG()                                                          \
    const int tid = threadIdx.x, lane = tid & 31, wid = tid >> 5;              \
    const int g = lane >> 2, tig = lane & 3;                                   \
    const int wm = wid >> 2, wn = wid & 3;                                     \
    const int m0 = blockIdx.y * 128, n0 = blockIdx.x * 128;                    \
    const uint32_t sbase = (uint32_t)__cvta_generic_to_shared(dynsm);          \
    const int row = tid >> 2, cc = (tid & 3) * 4;                              \
    const uint32_t dA0 = (uint32_t)(row * 20 + cc) * 4, dA1 = dA0 + 5120;      \
    const uint32_t foB = (uint32_t)(((lane & 7) + 8 * ((lane >> 3) & 1)) * 20  \
                                    + 4 * (lane >> 4)) * 4;                    \
    const uint32_t aB = (uint32_t)wm * 5120 + foB;                             \
    const uint32_t bB = (uint32_t)wn * 2560 + foB;                             \
    float acc[4][4][4];                                                        \
    for (int a_ = 0; a_ < 4; a_++)                                             \
        for (int b_ = 0; b_ < 4; b_++)                                         \
            for (int c_ = 0; c_ < 4; c_++) acc[a_][b_][c_] = 0.f;

#define GEMM_COMPUTE(bo)                                                       \
    _Pragma("unroll")                                                          \
    for (int ks = 0; ks < 2; ks++) {                                           \
        uint32_t ah[4][4], al[4][4], t0[4], t1[4], u0[4], u1[4];               \
        _Pragma("unroll")                                                      \
        for (int mi = 0; mi < 4; mi++) {                                       \
            ldsm4(ah[mi], sbase + (bo) + aB + mi * 1280 + ks * 32);            \
            ldsm4(al[mi], sbase + (bo) + 10240 + aB + mi * 1280 + ks * 32);    \
        }                                                                      \
        ldsm4(t0, sbase + (bo) + 20480 + bB + ks * 32);                        \
        ldsm4(t1, sbase + (bo) + 20480 + bB + 1280 + ks * 32);                 \
        ldsm4(u0, sbase + (bo) + 30720 + bB + ks * 32);                        \
        ldsm4(u1, sbase + (bo) + 30720 + bB + 1280 + ks * 32);                 \
        _Pragma("unroll")                                                      \
        for (int mi = 0; mi < 4; mi++) {                                       \
            mma16816(acc[mi][0], ah[mi], t0[0], t0[2]);                        \
            mma16816(acc[mi][0], al[mi], t0[0], t0[2]);                        \
            mma16816(acc[mi][0], ah[mi], u0[0], u0[2]);                        \
            mma16816(acc[mi][1], ah[mi], t0[1], t0[3]);                        \
            mma16816(acc[mi][1], al[mi], t0[1], t0[3]);                        \
            mma16816(acc[mi][1], ah[mi], u0[1], u0[3]);                        \
            mma16816(acc[mi][2], ah[mi], t1[0], t1[2]);                        \
            mma16816(acc[mi][2], al[mi], t1[0], t1[2]);                        \
            mma16816(acc[mi][2], ah[mi], u1[0], u1[2]);                        \
            mma16816(acc[mi][3], ah[mi], t1[1], t1[3]);                        \
            mma16816(acc[mi][3], al[mi], t1[1], t1[3]);                        \
            mma16816(acc[mi][3], ah[mi], u1[1], u1[3]);                        \
        }                                                                      \
    }

#define MAINLOOP_PIPE(STAGE)                                                   \
    STAGE(0, 0); CPCOMMIT();                                                   \
    STAGE(1, 1); CPCOMMIT();                                                   \
    for (int kt = 0; kt < 32; kt++) {                                          \
        CPWAIT1(); __syncthreads();                                            \
        if (kt + 2 < 32) { STAGE((kt + 2), ((kt + 2) % 3)); }                  \
        CPCOMMIT();                                                            \
        GEMM_COMPUTE((uint32_t)(kt % 3) * 40960u);                             \
    }

// standard A/B stage (both row-major u32 arrays with 512 cols)
#define STAGE_STD(kt, b)                                                       \
    { uint32_t sb = sbase + (uint32_t)(b) * 40960u;                            \
      int off = (kt) * 16;                                                     \
      cpa(sb + dA0,          pAh0 + off);                                      \
      cpa(sb + dA1,          pAh1 + off);                                      \
      cpa(sb + 10240 + dA0,  pAl0 + off);                                      \
      cpa(sb + 10240 + dA1,  pAl1 + off);                                      \
      cpa(sb + 20480 + dA0,  pBh0 + off);                                      \
      cpa(sb + 20480 + dA1,  pBh1 + off);                                      \
      cpa(sb + 30720 + dA0,  pBl0 + off);                                      \
      cpa(sb + 30720 + dA1,  pBl1 + off); }

__global__ __launch_bounds__(256) void pos_gemm() {
    GEMM_PROLOG();
    const uint32_t* pAh0 = g_Peh + (size_t)(m0 + row) * 512 + cc;
    const uint32_t* pAh1 = g_Peh + (size_t)(m0 + row + 64) * 512 + cc;
    const uint32_t* pAl0 = g_Pel + (size_t)(m0 + row) * 512 + cc;
    const uint32_t* pAl1 = g_Pel + (size_t)(m0 + row + 64) * 512 + cc;
    const uint32_t* pBh0 = g_WTh + (size_t)(n0 + row) * 512 + cc;
    const uint32_t* pBh1 = g_WTh + (size_t)(n0 + row + 64) * 512 + cc;
    const uint32_t* pBl0 = g_WTl + (size_t)(n0 + row) * 512 + cc;
    const uint32_t* pBl1 = g_WTl + (size_t)(n0 + row + 64) * 512 + cc;
    MAINLOOP_PIPE(STAGE_STD);
#pragma unroll
    for (int mi = 0; mi < 4; mi++)
#pragma unroll
        for (int nj = 0; nj < 4; nj++) {
            int m = m0 + wm * 64 + mi * 16 + g;
            int nn = n0 + wn * 32 + nj * 8 + 2 * tig;
            *(float2*)(g_pos + (size_t)m * 2048 + nn) = make_float2(acc[mi][nj][0], acc[mi][nj][1]);
            *(float2*)(g_pos + (size_t)(m + 8) * 2048 + nn) = make_float2(acc[mi][nj][2], acc[mi][nj][3]);
        }
}

__global__ __launch_bounds__(256) void qkv_gemm() {
    GEMM_PROLOG();
    const uint32_t* pAh0 = g_Xh + (size_t)(m0 + row) * 512 + cc;
    const uint32_t* pAh1 = g_Xh + (size_t)(m0 + row + 64) * 512 + cc;
    const uint32_t* pAl0 = g_Xl + (size_t)(m0 + row) * 512 + cc;
    const uint32_t* pAl1 = g_Xl + (size_t)(m0 + row + 64) * 512 + cc;
    const uint32_t* pBh0 = g_WTh + (size_t)(n0 + row) * 512 + cc;
    const uint32_t* pBh1 = g_WTh + (size_t)(n0 + row + 64) * 512 + cc;
    const uint32_t* pBl0 = g_WTl + (size_t)(n0 + row) * 512 + cc;
    const uint32_t* pBl1 = g_WTl + (size_t)(n0 + row + 64) * 512 + cc;
    MAINLOOP_PIPE(STAGE_STD);

    const int reg = n0 >> 10;   // 0=Q 1=K 2=V, uniform per block
#pragma unroll
    for (int mi = 0; mi < 4; mi++) {
#pragma unroll
        for (int nj = 0; nj < 4; nj++) {
            int m = m0 + wm * 64 + mi * 16 + g;
            int nn = n0 + wn * 32 + nj * 8 + 2 * tig;
            int bb = m >> 11, ss = m & 2047;
            float c0 = acc[mi][nj][0], c1 = acc[mi][nj][1];
            float c2 = acc[mi][nj][2], c3 = acc[mi][nj][3];
            if (reg < 2) {
                float2 pa = *(const float2*)(g_pos + (size_t)ss * 2048 + nn);
                float2 pb = *(const float2*)(g_pos + (size_t)(ss + 8) * 2048 + nn);
                c0 += pa.x; c1 += pa.y; c2 += pb.x; c3 += pb.y;
                if (reg == 0) { c0 *= 0.125f; c1 *= 0.125f; c2 *= 0.125f; c3 *= 0.125f; }
                int head = (nn >> 6) & 15, hp = (nn & 63) >> 1;
                size_t bn = (size_t)bb * 16 + head;
                size_t i0 = (bn * SEQ + ss) * 32 + hp;
                size_t i1 = (bn * SEQ + ss + 8) * 32 + hp;
                uint32_t h01, l01, h23, l23;
                split_pack(c0, c1, h01, l01);
                split_pack(c2, c3, h23, l23);
                if (reg == 0) { g_Qh[i0] = h01; g_Ql[i0] = l01; g_Qh[i1] = h23; g_Ql[i1] = l23; }
                else          { g_Kh[i0] = h01; g_Kl[i0] = l01; g_Kh[i1] = h23; g_Kl[i1] = l23; }
            } else {
                float o0 = __shfl_xor_sync(0xffffffffu, c0, 4);
                float o1 = __shfl_xor_sync(0xffffffffu, c1, 4);
                float o2 = __shfl_xor_sync(0xffffffffu, c2, 4);
                float o3 = __shfl_xor_sync(0xffffffffu, c3, 4);
                if ((g & 1) == 0) {
                    int head = (nn >> 6) & 15;
                    size_t bn = (size_t)bb * 16 + head;
                    int h0 = nn & 63;
                    int sp0 = ss >> 1;
                    uint32_t hi, lo;
                    size_t b0 = (bn * HEADD + h0) * 1024;
                    size_t b1 = (bn * HEADD + h0 + 1) * 1024;
                    split_pack(c0, o0, hi, lo); g_VTh[b0 + sp0] = hi;     g_VTl[b0 + sp0] = lo;
                    split_pack(c1, o1, hi, lo); g_VTh[b1 + sp0] = hi;     g_VTl[b1 + sp0] = lo;
                    split_pack(c2, o2, hi, lo); g_VTh[b0 + sp0 + 4] = hi; g_VTl[b0 + sp0 + 4] = lo;
                    split_pack(c3, o3, hi, lo); g_VTh[b1 + sp0 + 4] = hi; g_VTl[b1 + sp0 + 4] = lo;
                }
            }
        }
    }
}

#define STAGE_OUT(kt, b)                                                       \
    { uint32_t sb = sbase + (uint32_t)(b) * 40960u;                            \
      int head = (kt) >> 1;                                                    \
      int wv = ((kt) & 1) * 16 + cc;                                           \
      const uint32_t* a0h = g_Oh + baseO + (size_t)head * (SEQ * 32) + wv;     \
      const uint32_t* a0l = g_Ol + baseO + (size_t)head * (SEQ * 32) + wv;     \
      cpa(sb + dA0,          a0h);                                             \
      cpa(sb + dA1,          a0h + 64 * 32);                                   \
      cpa(sb + 10240 + dA0,  a0l);                                             \
      cpa(sb + 10240 + dA1,  a0l + 64 * 32);                                   \
      int off = (kt) * 16;                                                     \
      cpa(sb + 20480 + dA0,  pBh0 + off);                                      \
      cpa(sb + 20480 + dA1,  pBh1 + off);                                      \
      cpa(sb + 30720 + dA0,  pBl0 + off);                                      \
      cpa(sb + 30720 + dA1,  pBl1 + off); }

__global__ __launch_bounds__(256) void out_gemm(float* __restrict__ out) {
    GEMM_PROLOG();
    const int arow = m0 + row;
    const int bb = arow >> 11, ss = arow & 2047;
    const size_t baseO = ((size_t)bb * 16 * SEQ + ss) * 32;
    const uint32_t* pBh0 = g_WoTh + (size_t)(n0 + row) * 512 + cc;
    const uint32_t* pBh1 = g_WoTh + (size_t)(n0 + row + 64) * 512 + cc;
    const uint32_t* pBl0 = g_WoTl + (size_t)(n0 + row) * 512 + cc;
    const uint32_t* pBl1 = g_WoTl + (size_t)(n0 + row + 64) * 512 + cc;
    MAINLOOP_PIPE(STAGE_OUT);
#pragma unroll
    for (int mi = 0; mi < 4; mi++)
#pragma unroll
        for (int nj = 0; nj < 4; nj++) {
            int m = m0 + wm * 64 + mi * 16 + g;
            int nn = n0 + wn * 32 + nj * 8 + 2 * tig;
            *(float2*)(out + (size_t)m * HIDDEN + nn) = make_float2(acc[mi][nj][0], acc[mi][nj][1]);
            *(float2*)(out + (size_t)(m + 8) * HIDDEN + nn) = make_float2(acc[mi][nj][2], acc[mi][nj][3]);
        }
}

// ---------------- flash attention: ldmatrix fragments ----------------------
__global__ __launch_bounds__(128) void attn_kernel() {
    __shared__ __align__(16) uint32_t Kh[64][44], Kl[64][44];  // reused as P
    __shared__ __align__(16) uint32_t Vh[64][44], Vl[64][44];  // V^T [h][key-pair]
    uint32_t (*Ph)[44] = Kh;
    uint32_t (*Pl)[44] = Kl;

    const int tid = threadIdx.x, lane = tid & 31, w = tid >> 5;
    const int g = lane >> 2, tig = lane & 3;
    const int bn = blockIdx.x, qt = blockIdx.y;

    const uint32_t sKh = (uint32_t)__cvta_generic_to_shared(&Kh[0][0]);
    const uint32_t sKl = (uint32_t)__cvta_generic_to_shared(&Kl[0][0]);
    const uint32_t sVh = (uint32_t)__cvta_generic_to_shared(&Vh[0][0]);
    const uint32_t sVl = (uint32_t)__cvta_generic_to_shared(&Vl[0][0]);
    const uint32_t foA = (uint32_t)(((lane & 7) + 8 * ((lane >> 3) & 1)) * 176 + 16 * (lane >> 4));

    const int qr = qt * 64 + 16 * w + g;
    const uint32_t* qbh = g_Qh + ((size_t)bn * SEQ + qr) * 32 + tig;
    const uint32_t* qbl = g_Ql + ((size_t)bn * SEQ + qr) * 32 + tig;
    uint32_t qah[4][4], qal[4][4];
#pragma unroll
    for (int ks = 0; ks < 4; ks++) {
        qah[ks][0] = qbh[ks * 8];     qah[ks][1] = qbh[256 + ks * 8];
        qah[ks][2] = qbh[ks * 8 + 4]; qah[ks][3] = qbh[256 + ks * 8 + 4];
        qal[ks][0] = qbl[ks * 8];     qal[ks][1] = qbl[256 + ks * 8];
        qal[ks][2] = qbl[ks * 8 + 4]; qal[ks][3] = qbl[256 + ks * 8 + 4];
    }

    float o[8][4];
#pragma unroll
    for (int nt = 0; nt < 8; nt++)
#pragma unroll
        for (int c = 0; c < 4; c++) o[nt][c] = 0.f;
    float mrun0 = -1e30f, mrun1 = -1e30f, lrun0 = 0.f, lrun1 = 0.f;

    const int lrow = tid >> 1, cb = (tid & 1) * 16;
    const uint32_t* kgh = g_Kh + ((size_t)bn * SEQ + lrow) * 32 + cb;
    const uint32_t* kgl = g_Kl + ((size_t)bn * SEQ + lrow) * 32 + cb;
    const uint32_t* vgh = g_VTh + ((size_t)bn * HEADD + lrow) * 1024 + cb;
    const uint32_t* vgl = g_VTl + ((size_t)bn * HEADD + lrow) * 1024 + cb;

    for (int kt = 0; kt <= qt; kt++) {
        const int kbase = kt * 64;
        __syncthreads();
        {
            size_t ko = (size_t)kbase * 32, vo = (size_t)kt * 32;
#pragma unroll
            for (int i = 0; i < 4; i++) {
                *(uint4*)&Kh[lrow][cb + 4 * i] = *(const uint4*)(kgh + ko + 4 * i);
                *(uint4*)&Kl[lrow][cb + 4 * i] = *(const uint4*)(kgl + ko + 4 * i);
                *(uint4*)&Vh[lrow][cb + 4 * i] = *(const uint4*)(vgh + vo + 4 * i);
                *(uint4*)&Vl[lrow][cb + 4 * i] = *(const uint4*)(vgl + vo + 4 * i);
            }
        }
        __syncthreads();

        float sacc[8][4];
#pragma unroll
        for (int nt = 0; nt < 8; nt++)
#pragma unroll
            for (int c = 0; c < 4; c++) sacc[nt][c] = 0.f;
#pragma unroll
        for (int ks = 0; ks < 4; ks++) {
#pragma unroll
            for (int m = 0; m < 4; m++) {
                uint32_t tk[4], uk[4];
                ldsm4(tk, sKh + m * 2816 + ks * 32 + foA);
                ldsm4(uk, sKl + m * 2816 + ks * 32 + foA);
                mma16816(sacc[2 * m],     qah[ks], tk[0], tk[2]);
                mma16816(sacc[2 * m],     qal[ks], tk[0], tk[2]);
                mma16816(sacc[2 * m],     qah[ks], uk[0], uk[2]);
                mma16816(sacc[2 * m + 1], qah[ks], tk[1], tk[3]);
                mma16816(sacc[2 * m + 1], qal[ks], tk[1], tk[3]);
                mma16816(sacc[2 * m + 1], qah[ks], uk[1], uk[3]);
            }
        }

        if (kt == qt) {
#pragma unroll
            for (int nt = 0; nt < 8; nt++) {
                int kg = kbase + nt * 8 + 2 * tig;
                if (kg > qr)         sacc[nt][0] = -1e30f;
                if (kg + 1 > qr)     sacc[nt][1] = -1e30f;
                if (kg > qr + 8)     sacc[nt][2] = -1e30f;
                if (kg + 1 > qr + 8) sacc[nt][3] = -1e30f;
            }
        }

        float ml0 = -1e30f, ml1 = -1e30f;
#pragma unroll
        for (int nt = 0; nt < 8; nt++) {
            ml0 = fmaxf(ml0, fmaxf(sacc[nt][0], sacc[nt][1]));
            ml1 = fmaxf(ml1, fmaxf(sacc[nt][2], sacc[nt][3]));
        }
        ml0 = fmaxf(ml0, __shfl_xor_sync(0xffffffffu, ml0, 1));
        ml0 = fmaxf(ml0, __shfl_xor_sync(0xffffffffu, ml0, 2));
        ml1 = fmaxf(ml1, __shfl_xor_sync(0xffffffffu, ml1, 1));
        ml1 = fmaxf(ml1, __shfl_xor_sync(0xffffffffu, ml1, 2));
        float mn0 = fmaxf(mrun0, ml0), mn1 = fmaxf(mrun1, ml1);
        float scl0 = __expf(mrun0 - mn0), scl1 = __expf(mrun1 - mn1);
        mrun0 = mn0; mrun1 = mn1;
        float ls0 = 0.f, ls1 = 0.f;
#pragma unroll
        for (int nt = 0; nt < 8; nt++) {
            float p0 = __expf(sacc[nt][0] - mn0);
            float p1 = __expf(sacc[nt][1] - mn0);
            float p2 = __expf(sacc[nt][2] - mn1);
            float p3 = __expf(sacc[nt][3] - mn1);
            ls0 += p0 + p1; ls1 += p2 + p3;
            sacc[nt][0] = p0; sacc[nt][1] = p1; sacc[nt][2] = p2; sacc[nt][3] = p3;
            o[nt][0] *= scl0; o[nt][1] *= scl0; o[nt][2] *= scl1; o[nt][3] *= scl1;
        }
        lrun0 = lrun0 * scl0 + ls0;
        lrun1 = lrun1 * scl1 + ls1;

        __syncthreads();
#pragma unroll
        for (int nt = 0; nt < 8; nt++) {
            uint32_t hi, lo;
            split_pack(sacc[nt][0], sacc[nt][1], hi, lo);
            Ph[16 * w + g][nt * 4 + tig] = hi;      Pl[16 * w + g][nt * 4 + tig] = lo;
            split_pack(sacc[nt][2], sacc[nt][3], hi, lo);
            Ph[16 * w + g + 8][nt * 4 + tig] = hi;  Pl[16 * w + g + 8][nt * 4 + tig] = lo;
        }
        __syncwarp();

#pragma unroll
        for (int ks = 0; ks < 4; ks++) {
            uint32_t ph[4], pl[4];
            ldsm4(ph, sKh + w * 2816 + ks * 32 + foA);
            ldsm4(pl, sKl + w * 2816 + ks * 32 + foA);
#pragma unroll
            for (int m = 0; m < 4; m++) {
                uint32_t tv[4], uv[4];
                ldsm4(tv, sVh + m * 2816 + ks * 32 + foA);
                ldsm4(uv, sVl + m * 2816 + ks * 32 + foA);
                mma16816(o[2 * m],     ph, tv[0], tv[2]);
                mma16816(o[2 * m],     pl, tv[0], tv[2]);
                mma16816(o[2 * m],     ph, uv[0], uv[2]);
                mma16816(o[2 * m + 1], ph, tv[1], tv[3]);
                mma16816(o[2 * m + 1], pl, tv[1], tv[3]);
                mma16816(o[2 * m + 1], ph, uv[1], uv[3]);
            }
        }
    }

    lrun0 += __shfl_xor_sync(0xffffffffu, lrun0, 1);
    lrun0 += __shfl_xor_sync(0xffffffffu, lrun0, 2);
    lrun1 += __shfl_xor_sync(0xffffffffu, lrun1, 1);
    lrun1 += __shfl_xor_sync(0xffffffffu, lrun1, 2);
    float inv0 = 1.f / lrun0, inv1 = 1.f / lrun1;
    size_t ob0 = ((size_t)bn * SEQ + qr) * 32 + tig;
    size_t ob1 = ((size_t)bn * SEQ + qr + 8) * 32 + tig;
#pragma unroll
    for (int nt = 0; nt < 8; nt++) {
        uint32_t hi, lo;
        split_pack(o[nt][0] * inv0, o[nt][1] * inv0, hi, lo);
        g_Oh[ob0 + nt * 4] = hi;  g_Ol[ob0 + nt * 4] = lo;
        split_pack(o[nt][2] * inv1, o[nt][3] * inv1, hi, lo);
        g_Oh[ob1 + nt * 4] = hi;  g_Ol[ob1 + nt * 4] = lo;
    }
}

extern "C" void kernel_launch(void* const* d_in, const int* in_sizes, int n_in,
                              void* d_out, int out_size)
{
    const float* x    = (const float*)d_in[0];
    const float* pe   = (const float*)d_in[1];
    const float* Wqkv = (const float*)d_in[2];
    const float* Wo   = (const float*)d_in[3];
    float* out = (float*)d_out;

    const int SMEM_DYN = 3 * 40960;
    cudaFuncSetAttribute(pos_gemm, cudaFuncAttributeMaxDynamicSharedMemorySize, SMEM_DYN);
    cudaFuncSetAttribute(qkv_gemm, cudaFuncAttributeMaxDynamicSharedMemorySize, SMEM_DYN);
    cudaFuncSetAttribute(out_gemm, cudaFuncAttributeMaxDynamicSharedMemorySize, SMEM_DYN);

    cvt_x_kernel<<<(MTOK * 512 + SEQ * 512 + 255) / 256, 256>>>(x, pe);
    cvt_w_kernel<<<(4 * HIDDEN * 512 + 255) / 256, 256>>>(Wqkv, Wo);
    pos_gemm<<<dim3(2 * HIDDEN / 128, SEQ / 128), 256, SMEM_DYN>>>();
    qkv_gemm<<<dim3(3 * HIDDEN / 128, MTOK / 128), 256, SMEM_DYN>>>();
    attn_kernel<<<dim3(BNH, SEQ / 64), 128>>>();
    out_gemm<<<dim3(HIDDEN / 128, MTOK / 128), 256, SMEM_DYN>>>(out);
}

// round 9
// speedup vs baseline: 2.1227x; 1.1066x over previous
#include <cuda_runtime.h>
#include <cuda_bf16.h>
#include <cstdint>
#include <math.h>

#define HIDDEN 1024
#define NHEADS 16
#define HEADD  64
#define BATCH  4
#define SEQ    2048
#define MTOK   (BATCH*SEQ)
#define BNH    (BATCH*NHEADS)

// packed bf16 hi/lo pairs as u32
__device__ __align__(16) uint32_t g_Xh[MTOK*512],  g_Xl[MTOK*512];
__device__ __align__(16) uint32_t g_Peh[SEQ*512],  g_Pel[SEQ*512];
__device__ __align__(16) uint32_t g_WTh[3*HIDDEN*512], g_WTl[3*HIDDEN*512];
__device__ __align__(16) uint32_t g_WoTh[HIDDEN*512],  g_WoTl[HIDDEN*512];
__device__ __align__(16) float    g_pos[SEQ*2*HIDDEN];
__device__ __align__(16) uint32_t g_Qh[BNH*SEQ*32], g_Ql[BNH*SEQ*32];
__device__ __align__(16) uint32_t g_Kh[BNH*SEQ*32], g_Kl[BNH*SEQ*32];
__device__ __align__(16) uint32_t g_VTh[BNH*HEADD*1024], g_VTl[BNH*HEADD*1024];
__device__ __align__(16) uint32_t g_Oh[BNH*SEQ*32], g_Ol[BNH*SEQ*32];

__device__ __forceinline__ void split_pack(float a, float b, uint32_t& hi, uint32_t& lo) {
    __nv_bfloat16 ah = __float2bfloat16(a);
    __nv_bfloat16 bh = __float2bfloat16(b);
    __nv_bfloat16 al = __float2bfloat16(a - __bfloat162float(ah));
    __nv_bfloat16 bl = __float2bfloat16(b - __bfloat162float(bh));
    hi = (uint32_t)__bfloat16_as_ushort(ah) | ((uint32_t)__bfloat16_as_ushort(bh) << 16);
    lo = (uint32_t)__bfloat16_as_ushort(al) | ((uint32_t)__bfloat16_as_ushort(bl) << 16);
}

__device__ __forceinline__ void mma16816(float c[4], const uint32_t a[4],
                                         uint32_t b0, uint32_t b1) {
    asm volatile(
        "mma.sync.aligned.m16n8k16.row.col.f32.bf16.bf16.f32 "
        "{%0,%1,%2,%3},{%4,%5,%6,%7},{%8,%9},{%0,%1,%2,%3};\n"
        : "+f"(c[0]), "+f"(c[1]), "+f"(c[2]), "+f"(c[3])
        : "r"(a[0]), "r"(a[1]), "r"(a[2]), "r"(a[3]), "r"(b0), "r"(b1));
}

__device__ __forceinline__ void ldsm4(uint32_t r[4], uint32_t addr) {
    asm volatile("ldmatrix.sync.aligned.m8n8.x4.shared.b16 {%0,%1,%2,%3}, [%4];\n"
                 : "=r"(r[0]), "=r"(r[1]), "=r"(r[2]), "=r"(r[3]) : "r"(addr));
}

__device__ __forceinline__ void cpa(uint32_t saddr, const void* g) {
    asm volatile("cp.async.cg.shared.global [%0], [%1], 16;\n" :: "r"(saddr), "l"(g) : "memory");
}
#define CPCOMMIT() asm volatile("cp.async.commit_group;\n" ::: "memory")
#define CPWAIT1()  asm volatile("cp.async.wait_group 1;\n" ::: "memory")

__global__ void cvt_x_kernel(const float* __restrict__ x, const float* __restrict__ pe) {
    int i = blockIdx.x * blockDim.x + threadIdx.x;
    const int NX = MTOK * 512, NP = SEQ * 512;
    if (i < NX) {
        float2 v = ((const float2*)x)[i];
        split_pack(v.x, v.y, g_Xh[i], g_Xl[i]);
    } else if (i < NX + NP) {
        int j = i - NX;
        float2 v = ((const float2*)pe)[j];
        split_pack(v.x, v.y, g_Peh[j], g_Pel[j]);
    }
}

__global__ void cvt_w_kernel(const float* __restrict__ Wqkv, const float* __restrict__ Wo) {
    int i = blockIdx.x * blockDim.x + threadIdx.x;
    const int N1 = 3 * HIDDEN * 512, N2 = HIDDEN * 512;
    if (i < N1) {
        int n = i % (3 * HIDDEN), kp = i / (3 * HIDDEN);
        split_pack(Wqkv[(size_t)(2 * kp) * 3072 + n], Wqkv[(size_t)(2 * kp + 1) * 3072 + n],
                   g_WTh[(size_t)n * 512 + kp], g_WTl[(size_t)n * 512 + kp]);
    } else if (i < N1 + N2) {
        int j = i - N1;
        int n = j % HIDDEN, kp = j / HIDDEN;
        split_pack(Wo[(size_t)(2 * kp) * HIDDEN + n], Wo[(size_t)(2 * kp + 1) * HIDDEN + n],
                   g_WoTh[(size_t)n * 512 + kp], g_WoTl[(size_t)n * 512 + kp]);
    }
}

// ---------------- GEMM: 128x128 tile, K-step 32 floats, cp.async 2-stage ----
// dyn smem: 2 buffers x (Ah[128][20], Al, Bh, Bl) u32; 40960B each => 81920B.
// 2 CTAs per SM for cross-CTA latency hiding.
extern __shared__ __align__(16) uint32_t dynsm[];

#define GEMM_PROLOG()                                                          \
    const int tid = threadIdx.x, lane = tid & 31, wid = tid >> 5;              \
    const int g = lane >> 2, tig = lane & 3;                                   \
    const int wm = wid >> 2, wn = wid & 3;                                     \
    const int m0 = blockIdx.y * 128, n0 = blockIdx.x * 128;                    \
    const uint32_t sbase = (uint32_t)__cvta_generic_to_shared(dynsm);          \
    const int row = tid >> 2, cc = (tid & 3) * 4;                              \
    const uint32_t dA0 = (uint32_t)(row * 20 + cc) * 4, dA1 = dA0 + 5120;      \
    const uint32_t foB = (uint32_t)(((lane & 7) + 8 * ((lane >> 3) & 1)) * 20  \
                                    + 4 * (lane >> 4)) * 4;                    \
    const uint32_t aB = (uint32_t)wm * 5120 + foB;                             \
    const uint32_t bB = (uint32_t)wn * 2560 + foB;                             \
    float acc[4][4][4];                                                        \
    for (int a_ = 0; a_ < 4; a_++)                                             \
        for (int b_ = 0; b_ < 4; b_++)                                         \
            for (int c_ = 0; c_ < 4; c_++) acc[a_][b_][c_] = 0.f;

#define GEMM_COMPUTE(bo)                                                       \
    _Pragma("unroll")                                                          \
    for (int ks = 0; ks < 2; ks++) {                                           \
        uint32_t ah[4][4], al[4][4], t0[4], t1[4], u0[4], u1[4];               \
        _Pragma("unroll")                                                      \
        for (int mi = 0; mi < 4; mi++) {                                       \
            ldsm4(ah[mi], sbase + (bo) + aB + mi * 1280 + ks * 32);            \
            ldsm4(al[mi], sbase + (bo) + 10240 + aB + mi * 1280 + ks * 32);    \
        }                                                                      \
        ldsm4(t0, sbase + (bo) + 20480 + bB + ks * 32);                        \
        ldsm4(t1, sbase + (bo) + 20480 + bB + 1280 + ks * 32);                 \
        ldsm4(u0, sbase + (bo) + 30720 + bB + ks * 32);                        \
        ldsm4(u1, sbase + (bo) + 30720 + bB + 1280 + ks * 32);                 \
        _Pragma("unroll")                                                      \
        for (int mi = 0; mi < 4; mi++) {                                       \
            mma16816(acc[mi][0], ah[mi], t0[0], t0[2]);                        \
            mma16816(acc[mi][0], al[mi], t0[0], t0[2]);                        \
            mma16816(acc[mi][0], ah[mi], u0[0], u0[2]);                        \
            mma16816(acc[mi][1], ah[mi], t0[1], t0[3]);                        \
            mma16816(acc[mi][1], al[mi], t0[1], t0[3]);                        \
            mma16816(acc[mi][1], ah[mi], u0[1], u0[3]);                        \
            mma16816(acc[mi][2], ah[mi], t1[0], t1[2]);                        \
            mma16816(acc[mi][2], al[mi], t1[0], t1[2]);                        \
            mma16816(acc[mi][2], ah[mi], u1[0], u1[2]);                        \
            mma16816(acc[mi][3], ah[mi], t1[1], t1[3]);                        \
            mma16816(acc[mi][3], al[mi], t1[1], t1[3]);                        \
            mma16816(acc[mi][3], ah[mi], u1[1], u1[3]);                        \
        }                                                                      \
    }

// 2-stage double buffer: stage kt+1, wait for kt, compute kt, barrier.
#define MAINLOOP_PIPE(STAGE)                                                   \
    STAGE(0, 0); CPCOMMIT();                                                   \
    for (int kt = 0; kt < 32; kt++) {                                          \
        if (kt + 1 < 32) { STAGE((kt + 1), ((kt + 1) & 1)); }                  \
        CPCOMMIT();                                                            \
        CPWAIT1(); __syncthreads();                                            \
        GEMM_COMPUTE((uint32_t)(kt & 1) * 40960u);                             \
        __syncthreads();                                                       \
    }

// standard A/B stage (both row-major u32 arrays with 512 cols)
#define STAGE_STD(kt, b)                                                       \
    { uint32_t sb = sbase + (uint32_t)(b) * 40960u;                            \
      int off = (kt) * 16;                                                     \
      cpa(sb + dA0,          pAh0 + off);                                      \
      cpa(sb + dA1,          pAh1 + off);                                      \
      cpa(sb + 10240 + dA0,  pAl0 + off);                                      \
      cpa(sb + 10240 + dA1,  pAl1 + off);                                      \
      cpa(sb + 20480 + dA0,  pBh0 + off);                                      \
      cpa(sb + 20480 + dA1,  pBh1 + off);                                      \
      cpa(sb + 30720 + dA0,  pBl0 + off);                                      \
      cpa(sb + 30720 + dA1,  pBl1 + off); }

__global__ __launch_bounds__(256, 2) void pos_gemm() {
    GEMM_PROLOG();
    const uint32_t* pAh0 = g_Peh + (size_t)(m0 + row) * 512 + cc;
    const uint32_t* pAh1 = g_Peh + (size_t)(m0 + row + 64) * 512 + cc;
    const uint32_t* pAl0 = g_Pel + (size_t)(m0 + row) * 512 + cc;
    const uint32_t* pAl1 = g_Pel + (size_t)(m0 + row + 64) * 512 + cc;
    const uint32_t* pBh0 = g_WTh + (size_t)(n0 + row) * 512 + cc;
    const uint32_t* pBh1 = g_WTh + (size_t)(n0 + row + 64) * 512 + cc;
    const uint32_t* pBl0 = g_WTl + (size_t)(n0 + row) * 512 + cc;
    const uint32_t* pBl1 = g_WTl + (size_t)(n0 + row + 64) * 512 + cc;
    MAINLOOP_PIPE(STAGE_STD);
#pragma unroll
    for (int mi = 0; mi < 4; mi++)
#pragma unroll
        for (int nj = 0; nj < 4; nj++) {
            int m = m0 + wm * 64 + mi * 16 + g;
            int nn = n0 + wn * 32 + nj * 8 + 2 * tig;
            *(float2*)(g_pos + (size_t)m * 2048 + nn) = make_float2(acc[mi][nj][0], acc[mi][nj][1]);
            *(float2*)(g_pos + (size_t)(m + 8) * 2048 + nn) = make_float2(acc[mi][nj][2], acc[mi][nj][3]);
        }
}

__global__ __launch_bounds__(256, 2) void qkv_gemm() {
    GEMM_PROLOG();
    const uint32_t* pAh0 = g_Xh + (size_t)(m0 + row) * 512 + cc;
    const uint32_t* pAh1 = g_Xh + (size_t)(m0 + row + 64) * 512 + cc;
    const uint32_t* pAl0 = g_Xl + (size_t)(m0 + row) * 512 + cc;
    const uint32_t* pAl1 = g_Xl + (size_t)(m0 + row + 64) * 512 + cc;
    const uint32_t* pBh0 = g_WTh + (size_t)(n0 + row) * 512 + cc;
    const uint32_t* pBh1 = g_WTh + (size_t)(n0 + row + 64) * 512 + cc;
    const uint32_t* pBl0 = g_WTl + (size_t)(n0 + row) * 512 + cc;
    const uint32_t* pBl1 = g_WTl + (size_t)(n0 + row + 64) * 512 + cc;
    MAINLOOP_PIPE(STAGE_STD);

    const int reg = n0 >> 10;   // 0=Q 1=K 2=V, uniform per block
#pragma unroll
    for (int mi = 0; mi < 4; mi++) {
#pragma unroll
        for (int nj = 0; nj < 4; nj++) {
            int m = m0 + wm * 64 + mi * 16 + g;
            int nn = n0 + wn * 32 + nj * 8 + 2 * tig;
            int bb = m >> 11, ss = m & 2047;
            float c0 = acc[mi][nj][0], c1 = acc[mi][nj][1];
            float c2 = acc[mi][nj][2], c3 = acc[mi][nj][3];
            if (reg < 2) {
                float2 pa = *(const float2*)(g_pos + (size_t)ss * 2048 + nn);
                float2 pb = *(const float2*)(g_pos + (size_t)(ss + 8) * 2048 + nn);
                c0 += pa.x; c1 += pa.y; c2 += pb.x; c3 += pb.y;
                if (reg == 0) { c0 *= 0.125f; c1 *= 0.125f; c2 *= 0.125f; c3 *= 0.125f; }
                int head = (nn >> 6) & 15, hp = (nn & 63) >> 1;
                size_t bn = (size_t)bb * 16 + head;
                size_t i0 = (bn * SEQ + ss) * 32 + hp;
                size_t i1 = (bn * SEQ + ss + 8) * 32 + hp;
                uint32_t h01, l01, h23, l23;
                split_pack(c0, c1, h01, l01);
                split_pack(c2, c3, h23, l23);
                if (reg == 0) { g_Qh[i0] = h01; g_Ql[i0] = l01; g_Qh[i1] = h23; g_Ql[i1] = l23; }
                else          { g_Kh[i0] = h01; g_Kl[i0] = l01; g_Kh[i1] = h23; g_Kl[i1] = l23; }
            } else {
                float o0 = __shfl_xor_sync(0xffffffffu, c0, 4);
                float o1 = __shfl_xor_sync(0xffffffffu, c1, 4);
                float o2 = __shfl_xor_sync(0xffffffffu, c2, 4);
                float o3 = __shfl_xor_sync(0xffffffffu, c3, 4);
                if ((g & 1) == 0) {
                    int head = (nn >> 6) & 15;
                    size_t bn = (size_t)bb * 16 + head;
                    int h0 = nn & 63;
                    int sp0 = ss >> 1;
                    uint32_t hi, lo;
                    size_t b0 = (bn * HEADD + h0) * 1024;
                    size_t b1 = (bn * HEADD + h0 + 1) * 1024;
                    split_pack(c0, o0, hi, lo); g_VTh[b0 + sp0] = hi;     g_VTl[b0 + sp0] = lo;
                    split_pack(c1, o1, hi, lo); g_VTh[b1 + sp0] = hi;     g_VTl[b1 + sp0] = lo;
                    split_pack(c2, o2, hi, lo); g_VTh[b0 + sp0 + 4] = hi; g_VTl[b0 + sp0 + 4] = lo;
                    split_pack(c3, o3, hi, lo); g_VTh[b1 + sp0 + 4] = hi; g_VTl[b1 + sp0 + 4] = lo;
                }
            }
        }
    }
}

#define STAGE_OUT(kt, b)                                                       \
    { uint32_t sb = sbase + (uint32_t)(b) * 40960u;                            \
      int head = (kt) >> 1;                                                    \
      int wv = ((kt) & 1) * 16 + cc;                                           \
      const uint32_t* a0h = g_Oh + baseO + (size_t)head * (SEQ * 32) + wv;     \
      const uint32_t* a0l = g_Ol + baseO + (size_t)head * (SEQ * 32) + wv;     \
      cpa(sb + dA0,          a0h);                                             \
      cpa(sb + dA1,          a0h + 64 * 32);                                   \
      cpa(sb + 10240 + dA0,  a0l);                                             \
      cpa(sb + 10240 + dA1,  a0l + 64 * 32);                                   \
      int off = (kt) * 16;                                                     \
      cpa(sb + 20480 + dA0,  pBh0 + off);                                      \
      cpa(sb + 20480 + dA1,  pBh1 + off);                                      \
      cpa(sb + 30720 + dA0,  pBl0 + off);                                      \
      cpa(sb + 30720 + dA1,  pBl1 + off); }

__global__ __launch_bounds__(256, 2) void out_gemm(float* __restrict__ out) {
    GEMM_PROLOG();
    const int arow = m0 + row;
    const int bb = arow >> 11, ss = arow & 2047;
    const size_t baseO = ((size_t)bb * 16 * SEQ + ss) * 32;
    const uint32_t* pBh0 = g_WoTh + (size_t)(n0 + row) * 512 + cc;
    const uint32_t* pBh1 = g_WoTh + (size_t)(n0 + row + 64) * 512 + cc;
    const uint32_t* pBl0 = g_WoTl + (size_t)(n0 + row) * 512 + cc;
    const uint32_t* pBl1 = g_WoTl + (size_t)(n0 + row + 64) * 512 + cc;
    MAINLOOP_PIPE(STAGE_OUT);
#pragma unroll
    for (int mi = 0; mi < 4; mi++)
#pragma unroll
        for (int nj = 0; nj < 4; nj++) {
            int m = m0 + wm * 64 + mi * 16 + g;
            int nn = n0 + wn * 32 + nj * 8 + 2 * tig;
            *(float2*)(out + (size_t)m * HIDDEN + nn) = make_float2(acc[mi][nj][0], acc[mi][nj][1]);
            *(float2*)(out + (size_t)(m + 8) * HIDDEN + nn) = make_float2(acc[mi][nj][2], acc[mi][nj][3]);
        }
}

// ---------------- flash attention: ldmatrix fragments ----------------------
__global__ __launch_bounds__(128) void attn_kernel() {
    __shared__ __align__(16) uint32_t Kh[64][44], Kl[64][44];  // reused as P
    __shared__ __align__(16) uint32_t Vh[64][44], Vl[64][44];  // V^T [h][key-pair]
    uint32_t (*Ph)[44] = Kh;
    uint32_t (*Pl)[44] = Kl;

    const int tid = threadIdx.x, lane = tid & 31, w = tid >> 5;
    const int g = lane >> 2, tig = lane & 3;
    const int bn = blockIdx.x, qt = blockIdx.y;

    const uint32_t sKh = (uint32_t)__cvta_generic_to_shared(&Kh[0][0]);
    const uint32_t sKl = (uint32_t)__cvta_generic_to_shared(&Kl[0][0]);
    const uint32_t sVh = (uint32_t)__cvta_generic_to_shared(&Vh[0][0]);
    const uint32_t sVl = (uint32_t)__cvta_generic_to_shared(&Vl[0][0]);
    const uint32_t foA = (uint32_t)(((lane & 7) + 8 * ((lane >> 3) & 1)) * 176 + 16 * (lane >> 4));

    const int qr = qt * 64 + 16 * w + g;
    const uint32_t* qbh = g_Qh + ((size_t)bn * SEQ + qr) * 32 + tig;
    const uint32_t* qbl = g_Ql + ((size_t)bn * SEQ + qr) * 32 + tig;
    uint32_t qah[4][4], qal[4][4];
#pragma unroll
    for (int ks = 0; ks < 4; ks++) {
        qah[ks][0] = qbh[ks * 8];     qah[ks][1] = qbh[256 + ks * 8];
        qah[ks][2] = qbh[ks * 8 + 4]; qah[ks][3] = qbh[256 + ks * 8 + 4];
        qal[ks][0] = qbl[ks * 8];     qal[ks][1] = qbl[256 + ks * 8];
        qal[ks][2] = qbl[ks * 8 + 4]; qal[ks][3] = qbl[256 + ks * 8 + 4];
    }

    float o[8][4];
#pragma unroll
    for (int nt = 0; nt < 8; nt++)
#pragma unroll
        for (int c = 0; c < 4; c++) o[nt][c] = 0.f;
    float mrun0 = -1e30f, mrun1 = -1e30f, lrun0 = 0.f, lrun1 = 0.f;

    const int lrow = tid >> 1, cb = (tid & 1) * 16;
    const uint32_t* kgh = g_Kh + ((size_t)bn * SEQ + lrow) * 32 + cb;
    const uint32_t* kgl = g_Kl + ((size_t)bn * SEQ + lrow) * 32 + cb;
    const uint32_t* vgh = g_VTh + ((size_t)bn * HEADD + lrow) * 1024 + cb;
    const uint32_t* vgl = g_VTl + ((size_t)bn * HEADD + lrow) * 1024 + cb;

    for (int kt = 0; kt <= qt; kt++) {
        const int kbase = kt * 64;
        __syncthreads();
        {
            size_t ko = (size_t)kbase * 32, vo = (size_t)kt * 32;
#pragma unroll
            for (int i = 0; i < 4; i++) {
                *(uint4*)&Kh[lrow][cb + 4 * i] = *(const uint4*)(kgh + ko + 4 * i);
                *(uint4*)&Kl[lrow][cb + 4 * i] = *(const uint4*)(kgl + ko + 4 * i);
                *(uint4*)&Vh[lrow][cb + 4 * i] = *(const uint4*)(vgh + vo + 4 * i);
                *(uint4*)&Vl[lrow][cb + 4 * i] = *(const uint4*)(vgl + vo + 4 * i);
            }
        }
        __syncthreads();

        float sacc[8][4];
#pragma unroll
        for (int nt = 0; nt < 8; nt++)
#pragma unroll
            for (int c = 0; c < 4; c++) sacc[nt][c] = 0.f;
#pragma unroll
        for (int ks = 0; ks < 4; ks++) {
#pragma unroll
            for (int m = 0; m < 4; m++) {
                uint32_t tk[4], uk[4];
                ldsm4(tk, sKh + m * 2816 + ks * 32 + foA);
                ldsm4(uk, sKl + m * 2816 + ks * 32 + foA);
                mma16816(sacc[2 * m],     qah[ks], tk[0], tk[2]);
                mma16816(sacc[2 * m],     qal[ks], tk[0], tk[2]);
                mma16816(sacc[2 * m],     qah[ks], uk[0], uk[2]);
                mma16816(sacc[2 * m + 1], qah[ks], tk[1], tk[3]);
                mma16816(sacc[2 * m + 1], qal[ks], tk[1], tk[3]);
                mma16816(sacc[2 * m + 1], qah[ks], uk[1], uk[3]);
            }
        }

        if (kt == qt) {
#pragma unroll
            for (int nt = 0; nt < 8; nt++) {
                int kg = kbase + nt * 8 + 2 * tig;
                if (kg > qr)         sacc[nt][0] = -1e30f;
                if (kg + 1 > qr)     sacc[nt][1] = -1e30f;
                if (kg > qr + 8)     sacc[nt][2] = -1e30f;
                if (kg + 1 > qr + 8) sacc[nt][3] = -1e30f;
            }
        }

        float ml0 = -1e30f, ml1 = -1e30f;
#pragma unroll
        for (int nt = 0; nt < 8; nt++) {
            ml0 = fmaxf(ml0, fmaxf(sacc[nt][0], sacc[nt][1]));
            ml1 = fmaxf(ml1, fmaxf(sacc[nt][2], sacc[nt][3]));
        }
        ml0 = fmaxf(ml0, __shfl_xor_sync(0xffffffffu, ml0, 1));
        ml0 = fmaxf(ml0, __shfl_xor_sync(0xffffffffu, ml0, 2));
        ml1 = fmaxf(ml1, __shfl_xor_sync(0xffffffffu, ml1, 1));
        ml1 = fmaxf(ml1, __shfl_xor_sync(0xffffffffu, ml1, 2));
        float mn0 = fmaxf(mrun0, ml0), mn1 = fmaxf(mrun1, ml1);
        float scl0 = __expf(mrun0 - mn0), scl1 = __expf(mrun1 - mn1);
        mrun0 = mn0; mrun1 = mn1;
        float ls0 = 0.f, ls1 = 0.f;
#pragma unroll
        for (int nt = 0; nt < 8; nt++) {
            float p0 = __expf(sacc[nt][0] - mn0);
            float p1 = __expf(sacc[nt][1] - mn0);
            float p2 = __expf(sacc[nt][2] - mn1);
            float p3 = __expf(sacc[nt][3] - mn1);
            ls0 += p0 + p1; ls1 += p2 + p3;
            sacc[nt][0] = p0; sacc[nt][1] = p1; sacc[nt][2] = p2; sacc[nt][3] = p3;
            o[nt][0] *= scl0; o[nt][1] *= scl0; o[nt][2] *= scl1; o[nt][3] *= scl1;
        }
        lrun0 = lrun0 * scl0 + ls0;
        lrun1 = lrun1 * scl1 + ls1;

        __syncthreads();
#pragma unroll
        for (int nt = 0; nt < 8; nt++) {
            uint32_t hi, lo;
            split_pack(sacc[nt][0], sacc[nt][1], hi, lo);
            Ph[16 * w + g][nt * 4 + tig] = hi;      Pl[16 * w + g][nt * 4 + tig] = lo;
            split_pack(sacc[nt][2], sacc[nt][3], hi, lo);
            Ph[16 * w + g + 8][nt * 4 + tig] = hi;  Pl[16 * w + g + 8][nt * 4 + tig] = lo;
        }
        __syncwarp();

#pragma unroll
        for (int ks = 0; ks < 4; ks++) {
            uint32_t ph[4], pl[4];
            ldsm4(ph, sKh + w * 2816 + ks * 32 + foA);
            ldsm4(pl, sKl + w * 2816 + ks * 32 + foA);
#pragma unroll
            for (int m = 0; m < 4; m++) {
                uint32_t tv[4], uv[4];
                ldsm4(tv, sVh + m * 2816 + ks * 32 + foA);
                ldsm4(uv, sVl + m * 2816 + ks * 32 + foA);
                mma16816(o[2 * m],     ph, tv[0], tv[2]);
                mma16816(o[2 * m],     pl, tv[0], tv[2]);
                mma16816(o[2 * m],     ph, uv[0], uv[2]);
                mma16816(o[2 * m + 1], ph, tv[1], tv[3]);
                mma16816(o[2 * m + 1], pl, tv[1], tv[3]);
                mma16816(o[2 * m + 1], ph, uv[1], uv[3]);
            }
        }
    }

    lrun0 += __shfl_xor_sync(0xffffffffu, lrun0, 1);
    lrun0 += __shfl_xor_sync(0xffffffffu, lrun0, 2);
    lrun1 += __shfl_xor_sync(0xffffffffu, lrun1, 1);
    lrun1 += __shfl_xor_sync(0xffffffffu, lrun1, 2);
    float inv0 = 1.f / lrun0, inv1 = 1.f / lrun1;
    size_t ob0 = ((size_t)bn * SEQ + qr) * 32 + tig;
    size_t ob1 = ((size_t)bn * SEQ + qr + 8) * 32 + tig;
#pragma unroll
    for (int nt = 0; nt < 8; nt++) {
        uint32_t hi, lo;
        split_pack(o[nt][0] * inv0, o[nt][1] * inv0, hi, lo);
        g_Oh[ob0 + nt * 4] = hi;  g_Ol[ob0 + nt * 4] = lo;
        split_pack(o[nt][2] * inv1, o[nt][3] * inv1, hi, lo);
        g_Oh[ob1 + nt * 4] = hi;  g_Ol[ob1 + nt * 4] = lo;
    }
}

extern "C" void kernel_launch(void* const* d_in, const int* in_sizes, int n_in,
                              void* d_out, int out_size)
{
    const float* x    = (const float*)d_in[0];
    const float* pe   = (const float*)d_in[1];
    const float* Wqkv = (const float*)d_in[2];
    const float* Wo   = (const float*)d_in[3];
    float* out = (float*)d_out;

    const int SMEM_DYN = 2 * 40960;
    cudaFuncSetAttribute(pos_gemm, cudaFuncAttributeMaxDynamicSharedMemorySize, SMEM_DYN);
    cudaFuncSetAttribute(qkv_gemm, cudaFuncAttributeMaxDynamicSharedMemorySize, SMEM_DYN);
    cudaFuncSetAttribute(out_gemm, cudaFuncAttributeMaxDynamicSharedMemorySize, SMEM_DYN);

    cvt_x_kernel<<<(MTOK * 512 + SEQ * 512 + 255) / 256, 256>>>(x, pe);
    cvt_w_kernel<<<(4 * HIDDEN * 512 + 255) / 256, 256>>>(Wqkv, Wo);
    pos_gemm<<<dim3(2 * HIDDEN / 128, SEQ / 128), 256, SMEM_DYN>>>();
    qkv_gemm<<<dim3(3 * HIDDEN / 128, MTOK / 128), 256, SMEM_DYN>>>();
    attn_kernel<<<dim3(BNH, SEQ / 64), 128>>>();
    out_gemm<<<dim3(HIDDEN / 128, MTOK / 128), 256, SMEM_DYN>>>(out);
}

// round 10
// speedup vs baseline: 2.4842x; 1.1703x over previous
#include <cuda_runtime.h>
#include <cuda_bf16.h>
#include <cstdint>
#include <math.h>

#define HIDDEN 1024
#define NHEADS 16
#define HEADD  64
#define BATCH  4
#define SEQ    2048
#define MTOK   (BATCH*SEQ)
#define BNH    (BATCH*NHEADS)

// packed bf16 hi/lo pairs as u32
__device__ __align__(16) uint32_t g_Xh[MTOK*512],  g_Xl[MTOK*512];   // x
__device__ __align__(16) uint32_t g_XPh[MTOK*512], g_XPl[MTOK*512]; // x + pos
__device__ __align__(16) uint32_t g_WTh[3*HIDDEN*512], g_WTl[3*HIDDEN*512];
__device__ __align__(16) uint32_t g_WoTh[HIDDEN*512],  g_WoTl[HIDDEN*512];
__device__ __align__(16) uint32_t g_Qh[BNH*SEQ*32], g_Ql[BNH*SEQ*32];
__device__ __align__(16) uint32_t g_Kh[BNH*SEQ*32], g_Kl[BNH*SEQ*32];
__device__ __align__(16) uint32_t g_VTh[BNH*HEADD*1024], g_VTl[BNH*HEADD*1024];
__device__ __align__(16) uint32_t g_Oh[BNH*SEQ*32], g_Ol[BNH*SEQ*32];

__device__ __forceinline__ void split_pack(float a, float b, uint32_t& hi, uint32_t& lo) {
    __nv_bfloat16 ah = __float2bfloat16(a);
    __nv_bfloat16 bh = __float2bfloat16(b);
    __nv_bfloat16 al = __float2bfloat16(a - __bfloat162float(ah));
    __nv_bfloat16 bl = __float2bfloat16(b - __bfloat162float(bh));
    hi = (uint32_t)__bfloat16_as_ushort(ah) | ((uint32_t)__bfloat16_as_ushort(bh) << 16);
    lo = (uint32_t)__bfloat16_as_ushort(al) | ((uint32_t)__bfloat16_as_ushort(bl) << 16);
}

__device__ __forceinline__ void mma16816(float c[4], const uint32_t a[4],
                                         uint32_t b0, uint32_t b1) {
    asm volatile(
        "mma.sync.aligned.m16n8k16.row.col.f32.bf16.bf16.f32 "
        "{%0,%1,%2,%3},{%4,%5,%6,%7},{%8,%9},{%0,%1,%2,%3};\n"
        : "+f"(c[0]), "+f"(c[1]), "+f"(c[2]), "+f"(c[3])
        : "r"(a[0]), "r"(a[1]), "r"(a[2]), "r"(a[3]), "r"(b0), "r"(b1));
}

__device__ __forceinline__ void ldsm4(uint32_t r[4], uint32_t addr) {
    asm volatile("ldmatrix.sync.aligned.m8n8.x4.shared.b16 {%0,%1,%2,%3}, [%4];\n"
                 : "=r"(r[0]), "=r"(r[1]), "=r"(r[2]), "=r"(r[3]) : "r"(addr));
}

__device__ __forceinline__ void cpa(uint32_t saddr, const void* g) {
    asm volatile("cp.async.cg.shared.global [%0], [%1], 16;\n" :: "r"(saddr), "l"(g) : "memory");
}
#define CPCOMMIT() asm volatile("cp.async.commit_group;\n" ::: "memory")
#define CPWAIT1()  asm volatile("cp.async.wait_group 1;\n" ::: "memory")

// cvt: x pairs AND (x+pos) pairs in one pass
__global__ void cvt_x_kernel(const float* __restrict__ x, const float* __restrict__ pe) {
    int i = blockIdx.x * blockDim.x + threadIdx.x;
    if (i < MTOK * 512) {
        float2 v = ((const float2*)x)[i];
        split_pack(v.x, v.y, g_Xh[i], g_Xl[i]);
        int m = i >> 9, c = i & 511;
        int s = m & (SEQ - 1);
        float2 p = ((const float2*)pe)[s * 512 + c];
        split_pack(v.x + p.x, v.y + p.y, g_XPh[i], g_XPl[i]);
    }
}

__global__ void cvt_w_kernel(const float* __restrict__ Wqkv, const float* __restrict__ Wo) {
    int i = blockIdx.x * blockDim.x + threadIdx.x;
    const int N1 = 3 * HIDDEN * 512, N2 = HIDDEN * 512;
    if (i < N1) {
        int n = i % (3 * HIDDEN), kp = i / (3 * HIDDEN);
        split_pack(Wqkv[(size_t)(2 * kp) * 3072 + n], Wqkv[(size_t)(2 * kp + 1) * 3072 + n],
                   g_WTh[(size_t)n * 512 + kp], g_WTl[(size_t)n * 512 + kp]);
    } else if (i < N1 + N2) {
        int j = i - N1;
        int n = j % HIDDEN, kp = j / HIDDEN;
        split_pack(Wo[(size_t)(2 * kp) * HIDDEN + n], Wo[(size_t)(2 * kp + 1) * HIDDEN + n],
                   g_WoTh[(size_t)n * 512 + kp], g_WoTl[(size_t)n * 512 + kp]);
    }
}

// ---------------- GEMM: 128x128 tile, K-step 32 floats, cp.async 2-stage ----
extern __shared__ __align__(16) uint32_t dynsm[];

#define GEMM_PROLOG()                                                          \
    const int tid = threadIdx.x, lane = tid & 31, wid = tid >> 5;              \
    const int g = lane >> 2, tig = lane & 3;                                   \
    const int wm = wid >> 2, wn = wid & 3;                                     \
    const int m0 = blockIdx.y * 128, n0 = blockIdx.x * 128;                    \
    const uint32_t sbase = (uint32_t)__cvta_generic_to_shared(dynsm);          \
    const int row = tid >> 2, cc = (tid & 3) * 4;                              \
    const uint32_t dA0 = (uint32_t)(row * 20 + cc) * 4, dA1 = dA0 + 5120;      \
    const uint32_t foB = (uint32_t)(((lane & 7) + 8 * ((lane >> 3) & 1)) * 20  \
                                    + 4 * (lane >> 4)) * 4;                    \
    const uint32_t aB = (uint32_t)wm * 5120 + foB;                             \
    const uint32_t bB = (uint32_t)wn * 2560 + foB;                             \
    float acc[4][4][4];                                                        \
    for (int a_ = 0; a_ < 4; a_++)                                             \
        for (int b_ = 0; b_ < 4; b_++)                                         \
            for (int c_ = 0; c_ < 4; c_++) acc[a_][b_][c_] = 0.f;

#define GEMM_COMPUTE(bo)                                                       \
    _Pragma("unroll")                                                          \
    for (int ks = 0; ks < 2; ks++) {                                           \
        uint32_t ah[4][4], al[4][4], t0[4], t1[4], u0[4], u1[4];               \
        _Pragma("unroll")                                                      \
        for (int mi = 0; mi < 4; mi++) {                                       \
            ldsm4(ah[mi], sbase + (bo) + aB + mi * 1280 + ks * 32);            \
            ldsm4(al[mi], sbase + (bo) + 10240 + aB + mi * 1280 + ks * 32);    \
        }                                                                      \
        ldsm4(t0, sbase + (bo) + 20480 + bB + ks * 32);                        \
        ldsm4(t1, sbase + (bo) + 20480 + bB + 1280 + ks * 32);                 \
        ldsm4(u0, sbase + (bo) + 30720 + bB + ks * 32);                        \
        ldsm4(u1, sbase + (bo) + 30720 + bB + 1280 + ks * 32);                 \
        _Pragma("unroll")                                                      \
        for (int mi = 0; mi < 4; mi++) {                                       \
            mma16816(acc[mi][0], ah[mi], t0[0], t0[2]);                        \
            mma16816(acc[mi][0], al[mi], t0[0], t0[2]);                        \
            mma16816(acc[mi][0], ah[mi], u0[0], u0[2]);                        \
            mma16816(acc[mi][1], ah[mi], t0[1], t0[3]);                        \
            mma16816(acc[mi][1], al[mi], t0[1], t0[3]);                        \
            mma16816(acc[mi][1], ah[mi], u0[1], u0[3]);                        \
            mma16816(acc[mi][2], ah[mi], t1[0], t1[2]);                        \
            mma16816(acc[mi][2], al[mi], t1[0], t1[2]);                        \
            mma16816(acc[mi][2], ah[mi], u1[0], u1[2]);                        \
            mma16816(acc[mi][3], ah[mi], t1[1], t1[3]);                        \
            mma16816(acc[mi][3], al[mi], t1[1], t1[3]);                        \
            mma16816(acc[mi][3], ah[mi], u1[1], u1[3]);                        \
        }                                                                      \
    }

#define MAINLOOP_PIPE(STAGE)                                                   \
    STAGE(0, 0); CPCOMMIT();                                                   \
    for (int kt = 0; kt < 32; kt++) {                                          \
        if (kt + 1 < 32) { STAGE((kt + 1), ((kt + 1) & 1)); }                  \
        CPCOMMIT();                                                            \
        CPWAIT1(); __syncthreads();                                            \
        GEMM_COMPUTE((uint32_t)(kt & 1) * 40960u);                             \
        __syncthreads();                                                       \
    }

#define STAGE_STD(kt, b)                                                       \
    { uint32_t sb = sbase + (uint32_t)(b) * 40960u;                            \
      int off = (kt) * 16;                                                     \
      cpa(sb + dA0,          pAh0 + off);                                      \
      cpa(sb + dA1,          pAh1 + off);                                      \
      cpa(sb + 10240 + dA0,  pAl0 + off);                                      \
      cpa(sb + 10240 + dA1,  pAl1 + off);                                      \
      cpa(sb + 20480 + dA0,  pBh0 + off);                                      \
      cpa(sb + 20480 + dA1,  pBh1 + off);                                      \
      cpa(sb + 30720 + dA0,  pBl0 + off);                                      \
      cpa(sb + 30720 + dA1,  pBl1 + off); }

__global__ __launch_bounds__(256, 2) void qkv_gemm() {
    GEMM_PROLOG();
    const int reg = n0 >> 10;   // 0=Q 1=K 2=V, uniform per block
    const uint32_t* baseAh = (reg < 2) ? g_XPh : g_Xh;
    const uint32_t* baseAl = (reg < 2) ? g_XPl : g_Xl;
    const uint32_t* pAh0 = baseAh + (size_t)(m0 + row) * 512 + cc;
    const uint32_t* pAh1 = baseAh + (size_t)(m0 + row + 64) * 512 + cc;
    const uint32_t* pAl0 = baseAl + (size_t)(m0 + row) * 512 + cc;
    const uint32_t* pAl1 = baseAl + (size_t)(m0 + row + 64) * 512 + cc;
    const uint32_t* pBh0 = g_WTh + (size_t)(n0 + row) * 512 + cc;
    const uint32_t* pBh1 = g_WTh + (size_t)(n0 + row + 64) * 512 + cc;
    const uint32_t* pBl0 = g_WTl + (size_t)(n0 + row) * 512 + cc;
    const uint32_t* pBl1 = g_WTl + (size_t)(n0 + row + 64) * 512 + cc;
    MAINLOOP_PIPE(STAGE_STD);

#pragma unroll
    for (int mi = 0; mi < 4; mi++) {
#pragma unroll
        for (int nj = 0; nj < 4; nj++) {
            int m = m0 + wm * 64 + mi * 16 + g;
            int nn = n0 + wn * 32 + nj * 8 + 2 * tig;
            int bb = m >> 11, ss = m & 2047;
            float c0 = acc[mi][nj][0], c1 = acc[mi][nj][1];
            float c2 = acc[mi][nj][2], c3 = acc[mi][nj][3];
            if (reg < 2) {
                if (reg == 0) { c0 *= 0.125f; c1 *= 0.125f; c2 *= 0.125f; c3 *= 0.125f; }
                int head = (nn >> 6) & 15, hp = (nn & 63) >> 1;
                size_t bn = (size_t)bb * 16 + head;
                size_t i0 = (bn * SEQ + ss) * 32 + hp;
                size_t i1 = (bn * SEQ + ss + 8) * 32 + hp;
                uint32_t h01, l01, h23, l23;
                split_pack(c0, c1, h01, l01);
                split_pack(c2, c3, h23, l23);
                if (reg == 0) { g_Qh[i0] = h01; g_Ql[i0] = l01; g_Qh[i1] = h23; g_Ql[i1] = l23; }
                else          { g_Kh[i0] = h01; g_Kl[i0] = l01; g_Kh[i1] = h23; g_Kl[i1] = l23; }
            } else {
                float o0 = __shfl_xor_sync(0xffffffffu, c0, 4);
                float o1 = __shfl_xor_sync(0xffffffffu, c1, 4);
                float o2 = __shfl_xor_sync(0xffffffffu, c2, 4);
                float o3 = __shfl_xor_sync(0xffffffffu, c3, 4);
                if ((g & 1) == 0) {
                    int head = (nn >> 6) & 15;
                    size_t bn = (size_t)bb * 16 + head;
                    int h0 = nn & 63;
                    int sp0 = ss >> 1;
                    uint32_t hi, lo;
                    size_t b0 = (bn * HEADD + h0) * 1024;
                    size_t b1 = (bn * HEADD + h0 + 1) * 1024;
                    split_pack(c0, o0, hi, lo); g_VTh[b0 + sp0] = hi;     g_VTl[b0 + sp0] = lo;
                    split_pack(c1, o1, hi, lo); g_VTh[b1 + sp0] = hi;     g_VTl[b1 + sp0] = lo;
                    split_pack(c2, o2, hi, lo); g_VTh[b0 + sp0 + 4] = hi; g_VTl[b0 + sp0 + 4] = lo;
                    split_pack(c3, o3, hi, lo); g_VTh[b1 + sp0 + 4] = hi; g_VTl[b1 + sp0 + 4] = lo;
                }
            }
        }
    }
}

#define STAGE_OUT(kt, b)                                                       \
    { uint32_t sb = sbase + (uint32_t)(b) * 40960u;                            \
      int head = (kt) >> 1;                                                    \
      int wv = ((kt) & 1) * 16 + cc;                                           \
      const uint32_t* a0h = g_Oh + baseO + (size_t)head * (SEQ * 32) + wv;     \
      const uint32_t* a0l = g_Ol + baseO + (size_t)head * (SEQ * 32) + wv;     \
      cpa(sb + dA0,          a0h);                                             \
      cpa(sb + dA1,          a0h + 64 * 32);                                   \
      cpa(sb + 10240 + dA0,  a0l);                                             \
      cpa(sb + 10240 + dA1,  a0l + 64 * 32);                                   \
      int off = (kt) * 16;                                                     \
      cpa(sb + 20480 + dA0,  pBh0 + off);                                      \
      cpa(sb + 20480 + dA1,  pBh1 + off);                                      \
      cpa(sb + 30720 + dA0,  pBl0 + off);                                      \
      cpa(sb + 30720 + dA1,  pBl1 + off); }

__global__ __launch_bounds__(256, 2) void out_gemm(float* __restrict__ out) {
    GEMM_PROLOG();
    const int arow = m0 + row;
    const int bb = arow >> 11, ss = arow & 2047;
    const size_t baseO = ((size_t)bb * 16 * SEQ + ss) * 32;
    const uint32_t* pBh0 = g_WoTh + (size_t)(n0 + row) * 512 + cc;
    const uint32_t* pBh1 = g_WoTh + (size_t)(n0 + row + 64) * 512 + cc;
    const uint32_t* pBl0 = g_WoTl + (size_t)(n0 + row) * 512 + cc;
    const uint32_t* pBl1 = g_WoTl + (size_t)(n0 + row + 64) * 512 + cc;
    MAINLOOP_PIPE(STAGE_OUT);
#pragma unroll
    for (int mi = 0; mi < 4; mi++)
#pragma unroll
        for (int nj = 0; nj < 4; nj++) {
            int m = m0 + wm * 64 + mi * 16 + g;
            int nn = n0 + wn * 32 + nj * 8 + 2 * tig;
            *(float2*)(out + (size_t)m * HIDDEN + nn) = make_float2(acc[mi][nj][0], acc[mi][nj][1]);
            *(float2*)(out + (size_t)(m + 8) * HIDDEN + nn) = make_float2(acc[mi][nj][2], acc[mi][nj][3]);
        }
}

// ---------------- flash attention: 128-query blocks, 8 warps --------------
// dyn smem (u32): Kh[64][44]@0, Kl@2816, Vh@5632, Vl@8448, Ph[128][44]@11264, Pl@16896
#define ATTN_SMEM 90112

__global__ __launch_bounds__(256, 2) void attn_kernel() {
    uint32_t* Kh = dynsm;
    uint32_t* Kl = dynsm + 2816;
    uint32_t* Vh = dynsm + 5632;
    uint32_t* Vl = dynsm + 8448;
    uint32_t* Ph = dynsm + 11264;
    uint32_t* Pl = dynsm + 16896;

    const int tid = threadIdx.x, lane = tid & 31, w = tid >> 5;   // w 0..7
    const int g = lane >> 2, tig = lane & 3;
    const int bn = blockIdx.x, qb = blockIdx.y;                   // qb 0..15

    const uint32_t sbase = (uint32_t)__cvta_generic_to_shared(dynsm);
    const uint32_t sKh = sbase,          sKl = sbase + 11264;
    const uint32_t sVh = sbase + 22528,  sVl = sbase + 33792;
    const uint32_t sPh = sbase + 45056,  sPl = sbase + 67584;
    const uint32_t foA = (uint32_t)(((lane & 7) + 8 * ((lane >> 3) & 1)) * 176 + 16 * (lane >> 4));

    const int qr = qb * 128 + 16 * w + g;
    const uint32_t* qbh = g_Qh + ((size_t)bn * SEQ + qr) * 32 + tig;
    const uint32_t* qbl = g_Ql + ((size_t)bn * SEQ + qr) * 32 + tig;
    uint32_t qah[4][4], qal[4][4];
#pragma unroll
    for (int ks = 0; ks < 4; ks++) {
        qah[ks][0] = qbh[ks * 8];     qah[ks][1] = qbh[256 + ks * 8];
        qah[ks][2] = qbh[ks * 8 + 4]; qah[ks][3] = qbh[256 + ks * 8 + 4];
        qal[ks][0] = qbl[ks * 8];     qal[ks][1] = qbl[256 + ks * 8];
        qal[ks][2] = qbl[ks * 8 + 4]; qal[ks][3] = qbl[256 + ks * 8 + 4];
    }

    float o[8][4];
#pragma unroll
    for (int nt = 0; nt < 8; nt++)
#pragma unroll
        for (int c = 0; c < 4; c++) o[nt][c] = 0.f;
    float mrun0 = -1e30f, mrun1 = -1e30f, lrun0 = 0.f, lrun1 = 0.f;

    // K/V tile loads: 64 rows, 8 u32 per thread per array (256 threads)
    const int lrow = tid >> 2, cb = (tid & 3) * 8;
    const int sidx = lrow * 44 + cb;
    const uint32_t* kgh = g_Kh + ((size_t)bn * SEQ + lrow) * 32 + cb;
    const uint32_t* kgl = g_Kl + ((size_t)bn * SEQ + lrow) * 32 + cb;
    const uint32_t* vgh = g_VTh + ((size_t)bn * HEADD + lrow) * 1024 + cb;
    const uint32_t* vgl = g_VTl + ((size_t)bn * HEADD + lrow) * 1024 + cb;

    const int ntiles = 2 * qb + 2;
    for (int kt = 0; kt < ntiles; kt++) {
        const int kbase = kt * 64;
        __syncthreads();   // prior PV reads of V done before overwrite
        {
            size_t ko = (size_t)kbase * 32, vo = (size_t)kt * 32;
            *(uint4*)&Kh[sidx]     = *(const uint4*)(kgh + ko);
            *(uint4*)&Kh[sidx + 4] = *(const uint4*)(kgh + ko + 4);
            *(uint4*)&Kl[sidx]     = *(const uint4*)(kgl + ko);
            *(uint4*)&Kl[sidx + 4] = *(const uint4*)(kgl + ko + 4);
            *(uint4*)&Vh[sidx]     = *(const uint4*)(vgh + vo);
            *(uint4*)&Vh[sidx + 4] = *(const uint4*)(vgh + vo + 4);
            *(uint4*)&Vl[sidx]     = *(const uint4*)(vgl + vo);
            *(uint4*)&Vl[sidx + 4] = *(const uint4*)(vgl + vo + 4);
        }
        __syncthreads();

        // S = Qs @ K^T
        float sacc[8][4];
#pragma unroll
        for (int nt = 0; nt < 8; nt++)
#pragma unroll
            for (int c = 0; c < 4; c++) sacc[nt][c] = 0.f;
#pragma unroll
        for (int ks = 0; ks < 4; ks++) {
#pragma unroll
            for (int m = 0; m < 4; m++) {
                uint32_t tk[4], uk[4];
                ldsm4(tk, sKh + m * 2816 + ks * 32 + foA);
                ldsm4(uk, sKl + m * 2816 + ks * 32 + foA);
                mma16816(sacc[2 * m],     qah[ks], tk[0], tk[2]);
                mma16816(sacc[2 * m],     qal[ks], tk[0], tk[2]);
                mma16816(sacc[2 * m],     qah[ks], uk[0], uk[2]);
                mma16816(sacc[2 * m + 1], qah[ks], tk[1], tk[3]);
                mma16816(sacc[2 * m + 1], qal[ks], tk[1], tk[3]);
                mma16816(sacc[2 * m + 1], qah[ks], uk[1], uk[3]);
            }
        }

        if (kbase + 63 > qr) {   // causal mask (row-exact comparisons)
#pragma unroll
            for (int nt = 0; nt < 8; nt++) {
                int kg = kbase + nt * 8 + 2 * tig;
                if (kg > qr)         sacc[nt][0] = -1e30f;
                if (kg + 1 > qr)     sacc[nt][1] = -1e30f;
                if (kg > qr + 8)     sacc[nt][2] = -1e30f;
                if (kg + 1 > qr + 8) sacc[nt][3] = -1e30f;
            }
        }

        // online softmax
        float ml0 = -1e30f, ml1 = -1e30f;
#pragma unroll
        for (int nt = 0; nt < 8; nt++) {
            ml0 = fmaxf(ml0, fmaxf(sacc[nt][0], sacc[nt][1]));
            ml1 = fmaxf(ml1, fmaxf(sacc[nt][2], sacc[nt][3]));
        }
        ml0 = fmaxf(ml0, __shfl_xor_sync(0xffffffffu, ml0, 1));
        ml0 = fmaxf(ml0, __shfl_xor_sync(0xffffffffu, ml0, 2));
        ml1 = fmaxf(ml1, __shfl_xor_sync(0xffffffffu, ml1, 1));
        ml1 = fmaxf(ml1, __shfl_xor_sync(0xffffffffu, ml1, 2));
        float mn0 = fmaxf(mrun0, ml0), mn1 = fmaxf(mrun1, ml1);
        float scl0 = __expf(mrun0 - mn0), scl1 = __expf(mrun1 - mn1);
        mrun0 = mn0; mrun1 = mn1;
        float ls0 = 0.f, ls1 = 0.f;
#pragma unroll
        for (int nt = 0; nt < 8; nt++) {
            float p0 = __expf(sacc[nt][0] - mn0);
            float p1 = __expf(sacc[nt][1] - mn0);
            float p2 = __expf(sacc[nt][2] - mn1);
            float p3 = __expf(sacc[nt][3] - mn1);
            ls0 += p0 + p1; ls1 += p2 + p3;
            sacc[nt][0] = p0; sacc[nt][1] = p1; sacc[nt][2] = p2; sacc[nt][3] = p3;
            o[nt][0] *= scl0; o[nt][1] *= scl0; o[nt][2] *= scl1; o[nt][3] *= scl1;
        }
        lrun0 = lrun0 * scl0 + ls0;
        lrun1 = lrun1 * scl1 + ls1;

        // P store: dedicated buffer, rows warp-private -> no block barrier
#pragma unroll
        for (int nt = 0; nt < 8; nt++) {
            uint32_t hi, lo;
            split_pack(sacc[nt][0], sacc[nt][1], hi, lo);
            Ph[(16 * w + g) * 44 + nt * 4 + tig] = hi;
            Pl[(16 * w + g) * 44 + nt * 4 + tig] = lo;
            split_pack(sacc[nt][2], sacc[nt][3], hi, lo);
            Ph[(16 * w + g + 8) * 44 + nt * 4 + tig] = hi;
            Pl[(16 * w + g + 8) * 44 + nt * 4 + tig] = lo;
        }
        __syncwarp();

        // O += P @ V
#pragma unroll
        for (int ks = 0; ks < 4; ks++) {
            uint32_t ph[4], pl[4];
            ldsm4(ph, sPh + w * 2816 + ks * 32 + foA);
            ldsm4(pl, sPl + w * 2816 + ks * 32 + foA);
#pragma unroll
            for (int m = 0; m < 4; m++) {
                uint32_t tv[4], uv[4];
                ldsm4(tv, sVh + m * 2816 + ks * 32 + foA);
                ldsm4(uv, sVl + m * 2816 + ks * 32 + foA);
                mma16816(o[2 * m],     ph, tv[0], tv[2]);
                mma16816(o[2 * m],     pl, tv[0], tv[2]);
                mma16816(o[2 * m],     ph, uv[0], uv[2]);
                mma16816(o[2 * m + 1], ph, tv[1], tv[3]);
                mma16816(o[2 * m + 1], pl, tv[1], tv[3]);
                mma16816(o[2 * m + 1], ph, uv[1], uv[3]);
            }
        }
    }

    lrun0 += __shfl_xor_sync(0xffffffffu, lrun0, 1);
    lrun0 += __shfl_xor_sync(0xffffffffu, lrun0, 2);
    lrun1 += __shfl_xor_sync(0xffffffffu, lrun1, 1);
    lrun1 += __shfl_xor_sync(0xffffffffu, lrun1, 2);
    float inv0 = 1.f / lrun0, inv1 = 1.f / lrun1;
    size_t ob0 = ((size_t)bn * SEQ + qr) * 32 + tig;
    size_t ob1 = ((size_t)bn * SEQ + qr + 8) * 32 + tig;
#pragma unroll
    for (int nt = 0; nt < 8; nt++) {
        uint32_t hi, lo;
        split_pack(o[nt][0] * inv0, o[nt][1] * inv0, hi, lo);
        g_Oh[ob0 + nt * 4] = hi;  g_Ol[ob0 + nt * 4] = lo;
        split_pack(o[nt][2] * inv1, o[nt][3] * inv1, hi, lo);
        g_Oh[ob1 + nt * 4] = hi;  g_Ol[ob1 + nt * 4] = lo;
    }
}

extern "C" void kernel_launch(void* const* d_in, const int* in_sizes, int n_in,
                              void* d_out, int out_size)
{
    const float* x    = (const float*)d_in[0];
    const float* pe   = (const float*)d_in[1];
    const float* Wqkv = (const float*)d_in[2];
    const float* Wo   = (const float*)d_in[3];
    float* out = (float*)d_out;

    const int SMEM_DYN = 2 * 40960;
    cudaFuncSetAttribute(qkv_gemm, cudaFuncAttributeMaxDynamicSharedMemorySize, SMEM_DYN);
    cudaFuncSetAttribute(out_gemm, cudaFuncAttributeMaxDynamicSharedMemorySize, SMEM_DYN);
    cudaFuncSetAttribute(attn_kernel, cudaFuncAttributeMaxDynamicSharedMemorySize, ATTN_SMEM);

    cvt_x_kernel<<<(MTOK * 512 + 255) / 256, 256>>>(x, pe);
    cvt_w_kernel<<<(4 * HIDDEN * 512 + 255) / 256, 256>>>(Wqkv, Wo);
    qkv_gemm<<<dim3(3 * HIDDEN / 128, MTOK / 128), 256, SMEM_DYN>>>();
    attn_kernel<<<dim3(BNH, SEQ / 128), 256, ATTN_SMEM>>>();
    out_gemm<<<dim3(HIDDEN / 128, MTOK / 128), 256, SMEM_DYN>>>(out);
}